// round 7
// baseline (speedup 1.0000x reference)
#include <cuda_runtime.h>
#include <cstdint>

#define BB 32
#define TT 2048
#define FF 128
#define HH 512

// Scratch: precomputed input projection pre[b][t][h] = x W_ih^T + b_ih + b_hh
__device__ float g_pre[BB * TT * HH];   // 128 MiB
__device__ float g_v[HH];
__device__ float g_c;

// ---------------------------------------------------------------------------
// helpers
// ---------------------------------------------------------------------------
__device__ __forceinline__ uint32_t smem_u32(const void* p) {
    uint32_t a;
    asm("{ .reg .u64 t; cvta.to.shared.u64 t, %1; cvt.u32.u64 %0, t; }" : "=r"(a) : "l"(p));
    return a;
}
__device__ __forceinline__ uint32_t ctarank() {
    uint32_t r; asm("mov.u32 %0, %%cluster_ctarank;" : "=r"(r)); return r;
}
__device__ __forceinline__ uint32_t mapa_u32(uint32_t a, uint32_t r) {
    uint32_t o; asm("mapa.shared::cluster.u32 %0, %1, %2;" : "=r"(o) : "r"(a), "r"(r)); return o;
}
__device__ __forceinline__ void cluster_sync_() {
    asm volatile("barrier.cluster.arrive.aligned;" ::: "memory");
    asm volatile("barrier.cluster.wait.aligned;" ::: "memory");
}
__device__ __forceinline__ void fma2(unsigned long long& acc, unsigned long long a,
                                     unsigned long long b) {
    asm("fma.rn.f32x2 %0, %1, %2, %0;" : "+l"(acc) : "l"(a), "l"(b));
}
__device__ __forceinline__ float hsum2(unsigned long long a) {
    float lo = __uint_as_float((unsigned)(a & 0xffffffffull));
    float hi = __uint_as_float((unsigned)(a >> 32));
    return lo + hi;
}
__device__ __forceinline__ unsigned long long pk2(float lo, float hi) {
    return (unsigned long long)__float_as_uint(lo) |
           ((unsigned long long)__float_as_uint(hi) << 32);
}
__device__ __forceinline__ float ftanh(float x) {
    float e = __expf(2.0f * x);
    return 1.0f - __fdividef(2.0f, e + 1.0f);
}
// mbarrier ops
__device__ __forceinline__ void mbar_init(uint32_t a, uint32_t cnt) {
    asm volatile("mbarrier.init.shared.b64 [%0], %1;" :: "r"(a), "r"(cnt) : "memory");
}
__device__ __forceinline__ void mbar_arrive_expect(uint32_t a, uint32_t tx) {
    asm volatile("mbarrier.arrive.expect_tx.shared.b64 _, [%0], %1;" :: "r"(a), "r"(tx) : "memory");
}
__device__ __forceinline__ void mbar_wait(uint32_t a, uint32_t parity) {
    asm volatile(
        "{\n\t.reg .pred P;\n"
        "W_%=:\n\t"
        "mbarrier.try_wait.parity.acquire.cluster.shared::cta.b64 P, [%0], %1, 0x989680;\n\t"
        "@!P bra W_%=;\n\t"
        "}" :: "r"(a), "r"(parity) : "memory");
}
// bulk smem->remote-smem copy, tx-counted on the destination CTA's mbarrier
__device__ __forceinline__ void bulkcp(uint32_t rdst, uint32_t lsrc, uint32_t bytes,
                                       uint32_t rmbar) {
    asm volatile(
        "cp.async.bulk.shared::cluster.shared::cta.mbarrier::complete_tx::bytes "
        "[%0], [%1], %2, [%3];"
        :: "r"(rdst), "r"(lsrc), "r"(bytes), "r"(rmbar) : "memory");
}
__device__ __forceinline__ void fence_async_() {
    asm volatile("fence.proxy.async.shared::cta;" ::: "memory");
}
__device__ __forceinline__ void stc1(uint32_t a, float v) {
    asm volatile("st.shared::cluster.f32 [%0], %1;" :: "r"(a), "f"(v) : "memory");
}

// ---------------------------------------------------------------------------
// v = W2 @ W1 (R^512), c = b2 + W2.b1
// ---------------------------------------------------------------------------
__global__ void vc_kernel(const float* __restrict__ W1, const float* __restrict__ b1,
                          const float* __restrict__ W2, const float* __restrict__ b2) {
    __shared__ float w2s[FF];
    int tid = threadIdx.x;
    if (tid < FF) w2s[tid] = W2[tid];
    __syncthreads();
    if (tid < HH) {
        float s = 0.f;
#pragma unroll 16
        for (int f = 0; f < FF; ++f) s = fmaf(w2s[f], W1[f * HH + tid], s);
        g_v[tid] = s;
    }
    if (tid == 0) {
        float s = b2[0];
        for (int f = 0; f < FF; ++f) s = fmaf(w2s[f], b1[f], s);
        g_c = s;
    }
}

// ---------------------------------------------------------------------------
// Input projection GEMM: [B*T,128] @ [128,512]^T + bias -> g_pre.
// ---------------------------------------------------------------------------
__global__ void __launch_bounds__(256) pre_gemm(const float* __restrict__ x,
                                                const float* __restrict__ Wih,
                                                const float* __restrict__ bih,
                                                const float* __restrict__ bhh) {
    __shared__ float xsT[32][68];
    __shared__ float wsT[32][68];
    const int tid = threadIdx.x;
    const int tx = tid & 15, ty = tid >> 4;
    const int m0 = blockIdx.y << 6;
    const int n0 = blockIdx.x << 6;
    float acc[4][4] = {};
    for (int k0 = 0; k0 < FF; k0 += 32) {
#pragma unroll
        for (int i = 0; i < 8; ++i) {
            int e = (i << 8) + tid;
            int r = e >> 5, cc = e & 31;
            xsT[cc][r] = x[(size_t)(m0 + r) * FF + k0 + cc];
            wsT[cc][r] = Wih[(size_t)(n0 + r) * FF + k0 + cc];
        }
        __syncthreads();
#pragma unroll
        for (int kk = 0; kk < 32; ++kk) {
            float4 a = *(const float4*)&xsT[kk][ty << 2];
            float4 b = *(const float4*)&wsT[kk][tx << 2];
            acc[0][0] = fmaf(a.x, b.x, acc[0][0]); acc[0][1] = fmaf(a.x, b.y, acc[0][1]);
            acc[0][2] = fmaf(a.x, b.z, acc[0][2]); acc[0][3] = fmaf(a.x, b.w, acc[0][3]);
            acc[1][0] = fmaf(a.y, b.x, acc[1][0]); acc[1][1] = fmaf(a.y, b.y, acc[1][1]);
            acc[1][2] = fmaf(a.y, b.z, acc[1][2]); acc[1][3] = fmaf(a.y, b.w, acc[1][3]);
            acc[2][0] = fmaf(a.z, b.x, acc[2][0]); acc[2][1] = fmaf(a.z, b.y, acc[2][1]);
            acc[2][2] = fmaf(a.z, b.z, acc[2][2]); acc[2][3] = fmaf(a.z, b.w, acc[2][3]);
            acc[3][0] = fmaf(a.w, b.x, acc[3][0]); acc[3][1] = fmaf(a.w, b.y, acc[3][1]);
            acc[3][2] = fmaf(a.w, b.z, acc[3][2]); acc[3][3] = fmaf(a.w, b.w, acc[3][3]);
        }
        __syncthreads();
    }
    const int n = n0 + (tx << 2);
    float4 bias;
    bias.x = bih[n + 0] + bhh[n + 0];
    bias.y = bih[n + 1] + bhh[n + 1];
    bias.z = bih[n + 2] + bhh[n + 2];
    bias.w = bih[n + 3] + bhh[n + 3];
#pragma unroll
    for (int i = 0; i < 4; ++i) {
        int m = m0 + (ty << 2) + i;
        float4 o;
        o.x = acc[i][0] + bias.x;
        o.y = acc[i][1] + bias.y;
        o.z = acc[i][2] + bias.z;
        o.w = acc[i][3] + bias.w;
        *(float4*)&g_pre[(size_t)m * HH + n] = o;
    }
}

// ---------------------------------------------------------------------------
// Persistent recurrence: 16 clusters x 8 CTAs, cluster c owns batches 2c,2c+1.
// Thread (g=tid>>2, s=tid&3) owns row rank*64+g, cols [128s,128s+128) in regs.
// Publish: stage 64 rows (256 B) per batch, then 8 bulk copies per batch
// (cp.async.bulk S2S cluster) -> 16 mbarrier tx-updates/step instead of 512.
// Batches pipelined so DSMEM delivery hides under the other batch's compute.
// Head (sign count) distributed: rank (t&7) computes step t's dot.
// ---------------------------------------------------------------------------
#define SEG   132                 // padded floats per 128-col segment
#define HPAD  528                 // 4*SEG floats per batch vector
#define BAT_B 2112u               // HPAD*4 bytes
#define BUF_B 4224u               // 2*BAT_B
#define EXP_TX 2048u              // 8 peers * 256 B per batch-mbar per step

__global__ void __launch_bounds__(256, 1) __cluster_dims__(8, 1, 1)
rnn_kernel(const int* __restrict__ lengths, const float* __restrict__ Whh,
           float* __restrict__ out, int out_size) {
    // h index j lives at (j>>7)*SEG + (j&127)
    __shared__ __align__(16) float hbuf[3][2][HPAD];
    __shared__ __align__(16) float staging[3][2][64];
    __shared__ __align__(8) unsigned long long mbars[6];   // [batch*3 + buf]
    __shared__ float cntbuf[16];                           // [rank*2 + batch] on rank 0

    const int tid = threadIdx.x;
    const int lane = tid & 31;
    const int wid = tid >> 5;
    const uint32_t rank = ctarank();
    const int cl = blockIdx.x >> 3;
    const int b0 = cl * 2, b1 = b0 + 1;
    const int len0 = lengths[b0], len1 = lengths[b1];
    const int tmax = (len0 > len1) ? len0 : len1;

    const int g = tid >> 2;         // 0..63 : row within rank slice
    const int s = tid & 3;          // 0..3  : 128-col slice
    const int rowA = (int)rank * 64 + g;

    // ---- W_hh row -> 64 packed f32x2 regs (128 cols) ----
    unsigned long long w[64];
    {
        const double2* pW = (const double2*)(Whh + (size_t)rowA * HH + s * 128);
#pragma unroll
        for (int i = 0; i < 32; ++i) {
            double2 d = pW[i];
            w[2 * i]     = __double_as_longlong(d.x);
            w[2 * i + 1] = __double_as_longlong(d.y);
        }
    }

    // ---- head vector (warps 0/1 of every rank) ----
    unsigned long long vv[8];
    float cval = 0.f;
    int hoffv[8];
    if (wid < 2) {
#pragma unroll
        for (int c = 0; c < 8; ++c) {
            float2 t = *(const float2*)(g_v + c * 64 + 2 * lane);
            vv[c] = pk2(t.x, t.y);
            hoffv[c] = (c >> 1) * SEG + (c & 1) * 64 + 2 * lane;
        }
        cval = g_c;
    }

    // ---- init ----
    {
        float* hz = &hbuf[0][0][0];
        for (int i = tid; i < 2 * HPAD; i += 256) hz[i] = 0.f;
    }
    const uint32_t mb_local = smem_u32(&mbars[0]);
    if (tid == 0) {
#pragma unroll
        for (int k = 0; k < 6; ++k) mbar_init(mb_local + k * 8u, 1);
    }
    __syncthreads();
    cluster_sync_();
    if (tid == 0) {
#pragma unroll
        for (int k = 0; k < 6; ++k) mbar_arrive_expect(mb_local + k * 8u, EXP_TX);
    }

    // per-issuer remote addresses (tid<8: peer = tid)
    uint32_t peer_h = 0, peer_mb = 0;
    if (tid < 8) {
        uint32_t slice_off = (rank >> 1) * 528u + 256u * (rank & 1);
        peer_h  = mapa_u32(smem_u32(&hbuf[0][0][0]), (uint32_t)tid) + slice_off;
        peer_mb = mapa_u32(mb_local, (uint32_t)tid);
    }
    const uint32_t stg_base = smem_u32(&staging[0][0][0]);

    const float* pb0 = g_pre + (size_t)b0 * TT * HH;
    const float* pb1 = g_pre + (size_t)b1 * TT * HH;

    float hA0 = 0.f, hA1 = 0.f;
    int cnt = 0;                    // warp0: batch0, warp1: batch1, lane0
    int par0 = 0, par1 = 0, par2 = 0;

    float pc0 = pb0[rowA];
    float pc1 = pb1[rowA];

    int p3 = 0;
    for (int t = 0; t <= tmax; ++t) {
        const int q3 = (p3 == 2) ? 0 : p3 + 1;
        const int par = (p3 == 0) ? par0 : (p3 == 1) ? par1 : par2;
        const uint32_t mb0 = mb_local + (uint32_t)p3 * 8u;          // batch0, buf p3
        const uint32_t mb1 = mb_local + (uint32_t)(3 + p3) * 8u;    // batch1, buf p3

        // ---------- batch 0 ----------
        if (t > 0) {
            mbar_wait(mb0, (uint32_t)par);
            if (tid == 0) mbar_arrive_expect(mb0, EXP_TX);
        }
        if (t < tmax) {
            const int tn = (t + 1 < tmax) ? (t + 1) : t;
            float pn0 = pb0[(size_t)tn * HH + rowA];

            const ulonglong2* h = (const ulonglong2*)&hbuf[p3][0][s * SEG];
            unsigned long long a0 = 0ull, a1 = 0ull;
#pragma unroll
            for (int i = 0; i < 32; ++i) {            // FIXED: 32 (full 128 cols)
                ulonglong2 x = h[i];
                fma2(a0, w[2 * i], x.x);
                fma2(a1, w[2 * i + 1], x.y);
            }
            float sum = hsum2(a0) + hsum2(a1);
            sum += __shfl_xor_sync(0xffffffffu, sum, 1);
            sum += __shfl_xor_sync(0xffffffffu, sum, 2);
            float n = ftanh(pc0 + sum);
            if (t < len0) hA0 = n;
            if (s == 0) staging[q3][0][g] = hA0;
            __syncthreads();
            if (tid < 8) {
                fence_async_();
                bulkcp(peer_h + (uint32_t)q3 * BUF_B,
                       stg_base + (uint32_t)(q3 * 2 + 0) * 256u, 256u,
                       peer_mb + (uint32_t)q3 * 8u);
            }
            pc0 = pn0;
        }

        // ---------- batch 1 ----------
        if (t > 0) {
            mbar_wait(mb1, (uint32_t)par);
            if (tid == 0) mbar_arrive_expect(mb1, EXP_TX);
            if (p3 == 0) par0 ^= 1; else if (p3 == 1) par1 ^= 1; else par2 ^= 1;
        }
        if (t < tmax) {
            const int tn = (t + 1 < tmax) ? (t + 1) : t;
            float pn1 = pb1[(size_t)tn * HH + rowA];

            const ulonglong2* h = (const ulonglong2*)&hbuf[p3][1][s * SEG];
            unsigned long long a0 = 0ull, a1 = 0ull;
#pragma unroll
            for (int i = 0; i < 32; ++i) {            // FIXED: 32 (full 128 cols)
                ulonglong2 x = h[i];
                fma2(a0, w[2 * i], x.x);
                fma2(a1, w[2 * i + 1], x.y);
            }
            float sum = hsum2(a0) + hsum2(a1);
            sum += __shfl_xor_sync(0xffffffffu, sum, 1);
            sum += __shfl_xor_sync(0xffffffffu, sum, 2);
            float n = ftanh(pc1 + sum);
            if (t < len1) hA1 = n;
            if (s == 0) staging[q3][1][g] = hA1;
            __syncthreads();
            if (tid < 8) {
                fence_async_();
                bulkcp(peer_h + (uint32_t)q3 * BUF_B + BAT_B,
                       stg_base + (uint32_t)(q3 * 2 + 1) * 256u, 256u,
                       peer_mb + (uint32_t)(3 + q3) * 8u);
            }
            pc1 = pn1;
        }

        // ---------- distributed sign-count head: rank (t&7) handles step t-1 ----------
        if (t >= 1 && (int)rank == (t & 7) && wid < 2) {
            const int lenb = wid ? len1 : len0;
            const int tc = t - 1;
            if (tc < lenb) {
                const float* hb = &hbuf[p3][wid][0];
                unsigned long long acc = 0ull;
#pragma unroll
                for (int c = 0; c < 8; ++c) {
                    unsigned long long x = *(const unsigned long long*)(hb + hoffv[c]);
                    fma2(acc, vv[c], x);
                }
                float d = hsum2(acc);
#pragma unroll
                for (int m = 1; m < 32; m <<= 1) d += __shfl_xor_sync(0xffffffffu, d, m);
                if (lane == 0 && d + cval > 0.f) cnt++;
            }
        }

        p3 = q3;
    }

    // ---- gather distributed counts to rank 0 ----
    {
        const uint32_t cnt_rm = mapa_u32(smem_u32(&cntbuf[0]), 0u);
        if (wid < 2 && lane == 0) stc1(cnt_rm + (rank * 2u + (uint32_t)wid) * 4u, (float)cnt);
    }
    cluster_sync_();

    // ---- outputs: [counts (32)] then [h_final (32x512)] ----
    const int have_h = (out_size >= BB + BB * HH);
    if (rank == 0) {
        if (tid == 0) {
            float sum = 0.f;
#pragma unroll
            for (int r = 0; r < 8; ++r) sum += cntbuf[2 * r];
            out[b0] = sum;
        }
        if (tid == 32) {
            float sum = 0.f;
#pragma unroll
            for (int r = 0; r < 8; ++r) sum += cntbuf[2 * r + 1];
            out[b1] = sum;
        }
        if (have_h) {
            const int pf = tmax % 3;
#pragma unroll
            for (int k = 0; k < 4; ++k) {
                int j = tid * 4 + k;             // 0..1023
                int b = j >> 9, jj = j & 511;
                out[BB + (size_t)(b0 + b) * HH + jj] =
                    hbuf[pf][b][(jj >> 7) * SEG + (jj & 127)];
            }
        }
    }
}

// ---------------------------------------------------------------------------
// launch
// ---------------------------------------------------------------------------
extern "C" void kernel_launch(void* const* d_in, const int* in_sizes, int n_in,
                              void* d_out, int out_size) {
    const float* x     = (const float*)d_in[0];
    const int* lengths = (const int*)d_in[1];
    const float* W_ih  = (const float*)d_in[2];
    const float* W_hh  = (const float*)d_in[3];
    const float* b_ih  = (const float*)d_in[4];
    const float* b_hh  = (const float*)d_in[5];
    const float* W1    = (const float*)d_in[6];
    const float* b1    = (const float*)d_in[7];
    const float* W2    = (const float*)d_in[8];
    const float* b2    = (const float*)d_in[9];
    float* out = (float*)d_out;

    vc_kernel<<<1, 512>>>(W1, b1, W2, b2);

    dim3 ggrid(HH / 64, (BB * TT) / 64);   // (8, 1024)
    pre_gemm<<<ggrid, 256>>>(x, W_ih, b_ih, b_hh);

    rnn_kernel<<<128, 256>>>(lengths, W_hh, out, out_size);
}

// round 8
// speedup vs baseline: 1.0952x; 1.0952x over previous
#include <cuda_runtime.h>
#include <cstdint>

#define BB 32
#define TT 2048
#define FF 128
#define HH 512

// 128 MB scratch each
__device__ float g_pre[BB * TT * HH];    // pre[b][t][h] = x W_ih^T + b_ih + b_hh
__device__ float g_hout[BB * TT * HH];   // h(t) per batch (frozen past len)
__device__ float g_v[HH];
__device__ float g_c;

// ---------------------------------------------------------------------------
// helpers
// ---------------------------------------------------------------------------
__device__ __forceinline__ uint32_t smem_u32(const void* p) {
    uint32_t a;
    asm("{ .reg .u64 t; cvta.to.shared.u64 t, %1; cvt.u32.u64 %0, t; }" : "=r"(a) : "l"(p));
    return a;
}
__device__ __forceinline__ uint32_t ctarank() {
    uint32_t r; asm("mov.u32 %0, %%cluster_ctarank;" : "=r"(r)); return r;
}
__device__ __forceinline__ uint32_t mapa_u32(uint32_t a, uint32_t r) {
    uint32_t o; asm("mapa.shared::cluster.u32 %0, %1, %2;" : "=r"(o) : "r"(a), "r"(r)); return o;
}
__device__ __forceinline__ void cluster_sync_() {
    asm volatile("barrier.cluster.arrive.aligned;" ::: "memory");
    asm volatile("barrier.cluster.wait.aligned;" ::: "memory");
}
__device__ __forceinline__ void fma2(unsigned long long& acc, unsigned long long a,
                                     unsigned long long b) {
    asm("fma.rn.f32x2 %0, %1, %2, %0;" : "+l"(acc) : "l"(a), "l"(b));
}
__device__ __forceinline__ float hsum2(unsigned long long a) {
    float lo = __uint_as_float((unsigned)(a & 0xffffffffull));
    float hi = __uint_as_float((unsigned)(a >> 32));
    return lo + hi;
}
__device__ __forceinline__ float ftanh(float x) {
    float e = __expf(2.0f * x);
    return 1.0f - __fdividef(2.0f, e + 1.0f);
}
__device__ __forceinline__ void mbar_init(uint32_t a, uint32_t cnt) {
    asm volatile("mbarrier.init.shared.b64 [%0], %1;" :: "r"(a), "r"(cnt) : "memory");
}
__device__ __forceinline__ void mbar_wait(uint32_t a, uint32_t parity) {
    asm volatile(
        "{\n\t.reg .pred P;\n"
        "W_%=:\n\t"
        "mbarrier.try_wait.parity.acquire.cluster.shared::cta.b64 P, [%0], %1, 0x989680;\n\t"
        "@!P bra W_%=;\n\t"
        "}" :: "r"(a), "r"(parity) : "memory");
}
// remote arrive with cluster-scope release (covers prior DSMEM stores via bar.sync)
__device__ __forceinline__ void mbar_arrive_remote(uint32_t ra) {
    asm volatile("mbarrier.arrive.release.cluster.shared::cluster.b64 _, [%0];"
                 :: "r"(ra) : "memory");
}
// plain remote DSMEM vector store (no tx accounting)
__device__ __forceinline__ void stc4(uint32_t a, float4 v) {
    asm volatile("st.shared::cluster.v4.f32 [%0], {%1,%2,%3,%4};"
                 :: "r"(a), "f"(v.x), "f"(v.y), "f"(v.z), "f"(v.w) : "memory");
}

// ---------------------------------------------------------------------------
// v = W2 @ W1 (R^512), c = b2 + W2.b1 ; also zero the count outputs
// ---------------------------------------------------------------------------
__global__ void vc_kernel(const float* __restrict__ W1, const float* __restrict__ b1,
                          const float* __restrict__ W2, const float* __restrict__ b2,
                          float* __restrict__ out) {
    __shared__ float w2s[FF];
    int tid = threadIdx.x;
    if (tid < FF) w2s[tid] = W2[tid];
    if (tid < BB) out[tid] = 0.f;
    __syncthreads();
    if (tid < HH) {
        float s = 0.f;
#pragma unroll 16
        for (int f = 0; f < FF; ++f) s = fmaf(w2s[f], W1[f * HH + tid], s);
        g_v[tid] = s;
    }
    if (tid == 0) {
        float s = b2[0];
        for (int f = 0; f < FF; ++f) s = fmaf(w2s[f], b1[f], s);
        g_c = s;
    }
}

// ---------------------------------------------------------------------------
// Input projection GEMM: [B*T,128] @ [128,512]^T + bias -> g_pre.
// ---------------------------------------------------------------------------
__global__ void __launch_bounds__(256) pre_gemm(const float* __restrict__ x,
                                                const float* __restrict__ Wih,
                                                const float* __restrict__ bih,
                                                const float* __restrict__ bhh) {
    __shared__ float xsT[32][68];
    __shared__ float wsT[32][68];
    const int tid = threadIdx.x;
    const int tx = tid & 15, ty = tid >> 4;
    const int m0 = blockIdx.y << 6;
    const int n0 = blockIdx.x << 6;
    float acc[4][4] = {};
    for (int k0 = 0; k0 < FF; k0 += 32) {
#pragma unroll
        for (int i = 0; i < 8; ++i) {
            int e = (i << 8) + tid;
            int r = e >> 5, cc = e & 31;
            xsT[cc][r] = x[(size_t)(m0 + r) * FF + k0 + cc];
            wsT[cc][r] = Wih[(size_t)(n0 + r) * FF + k0 + cc];
        }
        __syncthreads();
#pragma unroll
        for (int kk = 0; kk < 32; ++kk) {
            float4 a = *(const float4*)&xsT[kk][ty << 2];
            float4 b = *(const float4*)&wsT[kk][tx << 2];
            acc[0][0] = fmaf(a.x, b.x, acc[0][0]); acc[0][1] = fmaf(a.x, b.y, acc[0][1]);
            acc[0][2] = fmaf(a.x, b.z, acc[0][2]); acc[0][3] = fmaf(a.x, b.w, acc[0][3]);
            acc[1][0] = fmaf(a.y, b.x, acc[1][0]); acc[1][1] = fmaf(a.y, b.y, acc[1][1]);
            acc[1][2] = fmaf(a.y, b.z, acc[1][2]); acc[1][3] = fmaf(a.y, b.w, acc[1][3]);
            acc[2][0] = fmaf(a.z, b.x, acc[2][0]); acc[2][1] = fmaf(a.z, b.y, acc[2][1]);
            acc[2][2] = fmaf(a.z, b.z, acc[2][2]); acc[2][3] = fmaf(a.z, b.w, acc[2][3]);
            acc[3][0] = fmaf(a.w, b.x, acc[3][0]); acc[3][1] = fmaf(a.w, b.y, acc[3][1]);
            acc[3][2] = fmaf(a.w, b.z, acc[3][2]); acc[3][3] = fmaf(a.w, b.w, acc[3][3]);
        }
        __syncthreads();
    }
    const int n = n0 + (tx << 2);
    float4 bias;
    bias.x = bih[n + 0] + bhh[n + 0];
    bias.y = bih[n + 1] + bhh[n + 1];
    bias.z = bih[n + 2] + bhh[n + 2];
    bias.w = bih[n + 3] + bhh[n + 3];
#pragma unroll
    for (int i = 0; i < 4; ++i) {
        int m = m0 + (ty << 2) + i;
        float4 o;
        o.x = acc[i][0] + bias.x;
        o.y = acc[i][1] + bias.y;
        o.z = acc[i][2] + bias.z;
        o.w = acc[i][3] + bias.w;
        *(float4*)&g_pre[(size_t)m * HH + n] = o;
    }
}

// ---------------------------------------------------------------------------
// Persistent recurrence: 16 clusters x 8 CTAs, cluster c owns batches 2c,2c+1.
// Thread (q=tid>>4, s=tid&15): rows [rank*64+4q, +4), cols [32s, +32) in regs.
// After a 4-level shfl reduce every lane has 4 complete rows -> one 16B plain
// DSMEM store per peer per batch. Completion: __syncthreads, then threads 0..7
// each do ONE release-arrive on peer tid's mbar (count=8). No tx accounting.
// h(t) also streamed to g_hout; sign-count head done in a post-kernel.
// ---------------------------------------------------------------------------
#define SLC   36                 // padded floats per 32-col slice
#define HB    576                // floats per batch vector (16*36)
#define BATB  2304u              // bytes per batch vector
#define BUFB  4608u              // bytes per buffer (2 batches)

__global__ void __launch_bounds__(256, 1) __cluster_dims__(8, 1, 1)
rnn_kernel(const int* __restrict__ lengths, const float* __restrict__ Whh) {
    // h index j lives at (j>>5)*SLC + (j&31)
    __shared__ __align__(16) float hbuf[3][2][HB];
    __shared__ __align__(8) unsigned long long mbars[3];

    const int tid = threadIdx.x;
    const uint32_t rank = ctarank();
    const int cl = blockIdx.x >> 3;
    const int b0 = cl * 2, b1 = b0 + 1;
    const int len0 = lengths[b0], len1 = lengths[b1];
    const int tmax = (len0 > len1) ? len0 : len1;

    const int q = tid >> 4;          // 0..15 : 4-row group
    const int s = tid & 15;          // 0..15 : 32-col slice
    const int rowBase = (int)rank * 64 + 4 * q;

    // ---- W_hh 4 rows x 32 cols -> 64 packed f32x2 regs ----
    unsigned long long w[64];
#pragma unroll
    for (int i = 0; i < 4; ++i) {
        const double2* pW = (const double2*)(Whh + (size_t)(rowBase + i) * HH + 32 * s);
#pragma unroll
        for (int k = 0; k < 8; ++k) {
            double2 d = pW[k];
            w[i * 16 + 2 * k]     = __double_as_longlong(d.x);
            w[i * 16 + 2 * k + 1] = __double_as_longlong(d.y);
        }
    }

    // ---- init: zero buf 0 (both batches), init mbarriers (count = 8 arrives) ----
    {
        float* hz = &hbuf[0][0][0];
        for (int i = tid; i < 2 * HB; i += 256) hz[i] = 0.f;
    }
    const uint32_t mb_local = smem_u32(&mbars[0]);
    if (tid == 0) {
        mbar_init(mb_local + 0, 8);
        mbar_init(mb_local + 8, 8);
        mbar_init(mb_local + 16, 8);
    }
    __syncthreads();
    cluster_sync_();                 // init + zero visible cluster-wide

    // remote destinations
    // row r lands at float (r>>5)*SLC + (r&31); our 4-row pack is contiguous.
    const uint32_t dst_off = ((2u * rank + (uint32_t)(q >> 3)) * SLC + 4u * (q & 7)) * 4u;
    uint32_t peer_h = 0, peer_mb = 0;
    if (s < 8)  peer_h  = mapa_u32(smem_u32(&hbuf[0][0][0]), (uint32_t)s) + dst_off;
    if (tid < 8) peer_mb = mapa_u32(mb_local, (uint32_t)tid);

    const float* pb0 = g_pre + (size_t)b0 * TT * HH;
    const float* pb1 = g_pre + (size_t)b1 * TT * HH;

    float4 hr0 = {0.f, 0.f, 0.f, 0.f};
    float4 hr1 = {0.f, 0.f, 0.f, 0.f};
    float4 pc0 = *(const float4*)(pb0 + rowBase);
    float4 pc1 = *(const float4*)(pb1 + rowBase);

    int parbits = 0;                 // parity of mbar k in bit k
    int p3 = 0;
    for (int t = 0; t < tmax; ++t) {
        const int q3 = (p3 == 2) ? 0 : p3 + 1;

        if (t > 0) {
            mbar_wait(mb_local + (uint32_t)p3 * 8u, (uint32_t)((parbits >> p3) & 1));
            parbits ^= 1 << p3;
        }

        // prefetch next pre
        const int tn = (t + 1 < tmax) ? (t + 1) : t;
        float4 pn0 = *(const float4*)(pb0 + (size_t)tn * HH + rowBase);
        float4 pn1 = *(const float4*)(pb1 + (size_t)tn * HH + rowBase);

        // matvec: 4 rows x 32 cols, both batches
        const ulonglong2* h0 = (const ulonglong2*)&hbuf[p3][0][SLC * s];
        const ulonglong2* h1 = (const ulonglong2*)&hbuf[p3][1][SLC * s];
        unsigned long long a00 = 0, a01 = 0, a02 = 0, a03 = 0;
        unsigned long long a10 = 0, a11 = 0, a12 = 0, a13 = 0;
#pragma unroll
        for (int k = 0; k < 8; ++k) {
            ulonglong2 x0 = h0[k];
            ulonglong2 x1 = h1[k];
            fma2(a00, w[2 * k],      x0.x); fma2(a00, w[2 * k + 1],      x0.y);
            fma2(a01, w[16 + 2 * k], x0.x); fma2(a01, w[16 + 2 * k + 1], x0.y);
            fma2(a02, w[32 + 2 * k], x0.x); fma2(a02, w[32 + 2 * k + 1], x0.y);
            fma2(a03, w[48 + 2 * k], x0.x); fma2(a03, w[48 + 2 * k + 1], x0.y);
            fma2(a10, w[2 * k],      x1.x); fma2(a10, w[2 * k + 1],      x1.y);
            fma2(a11, w[16 + 2 * k], x1.x); fma2(a11, w[16 + 2 * k + 1], x1.y);
            fma2(a12, w[32 + 2 * k], x1.x); fma2(a12, w[32 + 2 * k + 1], x1.y);
            fma2(a13, w[48 + 2 * k], x1.x); fma2(a13, w[48 + 2 * k + 1], x1.y);
        }
        float s00 = hsum2(a00), s01 = hsum2(a01), s02 = hsum2(a02), s03 = hsum2(a03);
        float s10 = hsum2(a10), s11 = hsum2(a11), s12 = hsum2(a12), s13 = hsum2(a13);
#pragma unroll
        for (int m = 1; m < 16; m <<= 1) {
            s00 += __shfl_xor_sync(0xffffffffu, s00, m);
            s01 += __shfl_xor_sync(0xffffffffu, s01, m);
            s02 += __shfl_xor_sync(0xffffffffu, s02, m);
            s03 += __shfl_xor_sync(0xffffffffu, s03, m);
            s10 += __shfl_xor_sync(0xffffffffu, s10, m);
            s11 += __shfl_xor_sync(0xffffffffu, s11, m);
            s12 += __shfl_xor_sync(0xffffffffu, s12, m);
            s13 += __shfl_xor_sync(0xffffffffu, s13, m);
        }
        float4 n0, n1;
        n0.x = ftanh(pc0.x + s00); n0.y = ftanh(pc0.y + s01);
        n0.z = ftanh(pc0.z + s02); n0.w = ftanh(pc0.w + s03);
        n1.x = ftanh(pc1.x + s10); n1.y = ftanh(pc1.y + s11);
        n1.z = ftanh(pc1.z + s12); n1.w = ftanh(pc1.w + s13);
        if (t < len0) hr0 = n0;
        if (t < len1) hr1 = n1;

        // publish: one 16B plain DSMEM store per peer per batch
        if (s < 8) {
            const uint32_t dst = peer_h + (uint32_t)q3 * BUFB;
            stc4(dst, hr0);
            stc4(dst + BATB, hr1);
        }
        // stream h(t) to global for the post-kernel head
        if (s == 8)
            *(float4*)(g_hout + (size_t)b0 * TT * HH + (size_t)t * HH + rowBase) = hr0;
        if (s == 9)
            *(float4*)(g_hout + (size_t)b1 * TT * HH + (size_t)t * HH + rowBase) = hr1;

        __syncthreads();
        if (tid < 8) mbar_arrive_remote(peer_mb + (uint32_t)q3 * 8u);

        pc0 = pn0; pc1 = pn1;
        p3 = q3;
    }

    cluster_sync_();   // drain in-flight DSMEM stores before any CTA exits
}

// ---------------------------------------------------------------------------
// Post-kernel head: counts = sum_t<len (h(t).v + c > 0), h_final = h[len-1].
// grid (4, BB): 4 t-range quarters per batch; counts via atomicAdd (exact ints).
// ---------------------------------------------------------------------------
__global__ void __launch_bounds__(256) count_kernel(const int* __restrict__ lengths,
                                                    float* __restrict__ out, int out_size) {
    const int b = blockIdx.y;
    const int quarter = blockIdx.x;
    const int len = lengths[b];
    const int t0 = quarter * (TT / 4), t1 = t0 + TT / 4;
    const int tid = threadIdx.x, lane = tid & 31, wid = tid >> 5;

    float4 v[4];
#pragma unroll
    for (int i = 0; i < 4; ++i) v[i] = *(const float4*)(g_v + lane * 16 + i * 4);
    const float c = g_c;
    const float* hb = g_hout + (size_t)b * TT * HH;

    const int tend = (t1 < len) ? t1 : len;
    int cnt = 0;
    for (int t = t0 + wid; t < tend; t += 8) {
        const float4* hp = (const float4*)(hb + (size_t)t * HH + lane * 16);
        float d = 0.f;
#pragma unroll
        for (int i = 0; i < 4; ++i) {
            float4 h4 = hp[i];
            d = fmaf(h4.x, v[i].x, d); d = fmaf(h4.y, v[i].y, d);
            d = fmaf(h4.z, v[i].z, d); d = fmaf(h4.w, v[i].w, d);
        }
#pragma unroll
        for (int m = 1; m < 32; m <<= 1) d += __shfl_xor_sync(0xffffffffu, d, m);
        if (lane == 0 && d + c > 0.f) cnt++;
    }
    __shared__ int wcnt[8];
    if (lane == 0) wcnt[wid] = cnt;
    __syncthreads();
    if (tid == 0) {
        int sum = 0;
#pragma unroll
        for (int i = 0; i < 8; ++i) sum += wcnt[i];
        if (sum) atomicAdd(&out[b], (float)sum);
    }

    if (out_size >= BB + BB * HH) {
        const int tf = len - 1;
        if (tf >= t0 && tf < t1) {
            for (int j = tid; j < HH; j += 256)
                out[BB + (size_t)b * HH + j] = hb[(size_t)tf * HH + j];
        }
    }
}

// ---------------------------------------------------------------------------
// launch
// ---------------------------------------------------------------------------
extern "C" void kernel_launch(void* const* d_in, const int* in_sizes, int n_in,
                              void* d_out, int out_size) {
    const float* x     = (const float*)d_in[0];
    const int* lengths = (const int*)d_in[1];
    const float* W_ih  = (const float*)d_in[2];
    const float* W_hh  = (const float*)d_in[3];
    const float* b_ih  = (const float*)d_in[4];
    const float* b_hh  = (const float*)d_in[5];
    const float* W1    = (const float*)d_in[6];
    const float* b1    = (const float*)d_in[7];
    const float* W2    = (const float*)d_in[8];
    const float* b2    = (const float*)d_in[9];
    float* out = (float*)d_out;

    vc_kernel<<<1, 512>>>(W1, b1, W2, b2, out);

    dim3 ggrid(HH / 64, (BB * TT) / 64);   // (8, 1024)
    pre_gemm<<<ggrid, 256>>>(x, W_ih, b_ih, b_hh);

    rnn_kernel<<<128, 256>>>(lengths, W_hh);

    count_kernel<<<dim3(4, BB), 256>>>(lengths, out, out_size);
}

// round 11
// speedup vs baseline: 1.1299x; 1.0317x over previous
#include <cuda_runtime.h>
#include <cstdint>

#define BB 32
#define TT 2048
#define FF 128
#define HH 512

// 128 MB scratch each
__device__ float g_pre[BB * TT * HH];    // pre[b][t][h] = x W_ih^T + b_ih + b_hh
__device__ float g_hout[BB * TT * HH];   // h(t) per batch (frozen past len)
__device__ float g_v[HH];
__device__ float g_c;

// ---------------------------------------------------------------------------
// helpers
// ---------------------------------------------------------------------------
__device__ __forceinline__ uint32_t smem_u32(const void* p) {
    uint32_t a;
    asm("{ .reg .u64 t; cvta.to.shared.u64 t, %1; cvt.u32.u64 %0, t; }" : "=r"(a) : "l"(p));
    return a;
}
__device__ __forceinline__ uint32_t ctarank() {
    uint32_t r; asm("mov.u32 %0, %%cluster_ctarank;" : "=r"(r)); return r;
}
__device__ __forceinline__ uint32_t mapa_u32(uint32_t a, uint32_t r) {
    uint32_t o; asm("mapa.shared::cluster.u32 %0, %1, %2;" : "=r"(o) : "r"(a), "r"(r)); return o;
}
__device__ __forceinline__ void cluster_sync_() {
    asm volatile("barrier.cluster.arrive.aligned;" ::: "memory");
    asm volatile("barrier.cluster.wait.aligned;" ::: "memory");
}
__device__ __forceinline__ void fma2(unsigned long long& acc, unsigned long long a,
                                     unsigned long long b) {
    asm("fma.rn.f32x2 %0, %1, %2, %0;" : "+l"(acc) : "l"(a), "l"(b));
}
__device__ __forceinline__ float hsum2(unsigned long long a) {
    float lo = __uint_as_float((unsigned)(a & 0xffffffffull));
    float hi = __uint_as_float((unsigned)(a >> 32));
    return lo + hi;
}
__device__ __forceinline__ float ftanh(float x) {
    float e = __expf(2.0f * x);
    return 1.0f - __fdividef(2.0f, e + 1.0f);
}
__device__ __forceinline__ void mbar_init(uint32_t a, uint32_t cnt) {
    asm volatile("mbarrier.init.shared.b64 [%0], %1;" :: "r"(a), "r"(cnt) : "memory");
}
__device__ __forceinline__ void mbar_wait(uint32_t a, uint32_t parity) {
    asm volatile(
        "{\n\t.reg .pred P;\n"
        "W_%=:\n\t"
        "mbarrier.try_wait.parity.acquire.cluster.shared::cta.b64 P, [%0], %1, 0x989680;\n\t"
        "@!P bra W_%=;\n\t"
        "}" :: "r"(a), "r"(parity) : "memory");
}
// remote arrive with cluster-scope release (covers prior DSMEM stores via bar.sync)
__device__ __forceinline__ void mbar_arrive_remote(uint32_t ra) {
    asm volatile("mbarrier.arrive.release.cluster.shared::cluster.b64 _, [%0];"
                 :: "r"(ra) : "memory");
}
// plain remote DSMEM 8B vector store (no tx accounting)
__device__ __forceinline__ void stc2(uint32_t a, float x, float y) {
    asm volatile("st.shared::cluster.v2.f32 [%0], {%1,%2};"
                 :: "r"(a), "f"(x), "f"(y) : "memory");
}

// dummy kernel for ncu launch-index alignment (puts rnn_kernel at skip index 5)
__global__ void dummy_k() {}

// ---------------------------------------------------------------------------
// v = W2 @ W1 (R^512), c = b2 + W2.b1 ; also zero the count outputs
// ---------------------------------------------------------------------------
__global__ void vc_kernel(const float* __restrict__ W1, const float* __restrict__ b1,
                          const float* __restrict__ W2, const float* __restrict__ b2,
                          float* __restrict__ out) {
    __shared__ float w2s[FF];
    int tid = threadIdx.x;
    if (tid < FF) w2s[tid] = W2[tid];
    if (tid < BB) out[tid] = 0.f;
    __syncthreads();
    if (tid < HH) {
        float s = 0.f;
#pragma unroll 16
        for (int f = 0; f < FF; ++f) s = fmaf(w2s[f], W1[f * HH + tid], s);
        g_v[tid] = s;
    }
    if (tid == 0) {
        float s = b2[0];
        for (int f = 0; f < FF; ++f) s = fmaf(w2s[f], b1[f], s);
        g_c = s;
    }
}

// ---------------------------------------------------------------------------
// Input projection GEMM: [B*T,128] @ [128,512]^T + bias -> g_pre.
// ---------------------------------------------------------------------------
__global__ void __launch_bounds__(256) pre_gemm(const float* __restrict__ x,
                                                const float* __restrict__ Wih,
                                                const float* __restrict__ bih,
                                                const float* __restrict__ bhh) {
    __shared__ float xsT[32][68];
    __shared__ float wsT[32][68];
    const int tid = threadIdx.x;
    const int tx = tid & 15, ty = tid >> 4;
    const int m0 = blockIdx.y << 6;
    const int n0 = blockIdx.x << 6;
    float acc[4][4] = {};
    for (int k0 = 0; k0 < FF; k0 += 32) {
#pragma unroll
        for (int i = 0; i < 8; ++i) {
            int e = (i << 8) + tid;
            int r = e >> 5, cc = e & 31;
            xsT[cc][r] = x[(size_t)(m0 + r) * FF + k0 + cc];
            wsT[cc][r] = Wih[(size_t)(n0 + r) * FF + k0 + cc];
        }
        __syncthreads();
#pragma unroll
        for (int kk = 0; kk < 32; ++kk) {
            float4 a = *(const float4*)&xsT[kk][ty << 2];
            float4 b = *(const float4*)&wsT[kk][tx << 2];
            acc[0][0] = fmaf(a.x, b.x, acc[0][0]); acc[0][1] = fmaf(a.x, b.y, acc[0][1]);
            acc[0][2] = fmaf(a.x, b.z, acc[0][2]); acc[0][3] = fmaf(a.x, b.w, acc[0][3]);
            acc[1][0] = fmaf(a.y, b.x, acc[1][0]); acc[1][1] = fmaf(a.y, b.y, acc[1][1]);
            acc[1][2] = fmaf(a.y, b.z, acc[1][2]); acc[1][3] = fmaf(a.y, b.w, acc[1][3]);
            acc[2][0] = fmaf(a.z, b.x, acc[2][0]); acc[2][1] = fmaf(a.z, b.y, acc[2][1]);
            acc[2][2] = fmaf(a.z, b.z, acc[2][2]); acc[2][3] = fmaf(a.z, b.w, acc[2][3]);
            acc[3][0] = fmaf(a.w, b.x, acc[3][0]); acc[3][1] = fmaf(a.w, b.y, acc[3][1]);
            acc[3][2] = fmaf(a.w, b.z, acc[3][2]); acc[3][3] = fmaf(a.w, b.w, acc[3][3]);
        }
        __syncthreads();
    }
    const int n = n0 + (tx << 2);
    float4 bias;
    bias.x = bih[n + 0] + bhh[n + 0];
    bias.y = bih[n + 1] + bhh[n + 1];
    bias.z = bih[n + 2] + bhh[n + 2];
    bias.w = bih[n + 3] + bhh[n + 3];
#pragma unroll
    for (int i = 0; i < 4; ++i) {
        int m = m0 + (ty << 2) + i;
        float4 o;
        o.x = acc[i][0] + bias.x;
        o.y = acc[i][1] + bias.y;
        o.z = acc[i][2] + bias.z;
        o.w = acc[i][3] + bias.w;
        *(float4*)&g_pre[(size_t)m * HH + n] = o;
    }
}

// ---------------------------------------------------------------------------
// Persistent recurrence: 16 clusters x 8 CTAs, cluster c owns batches 2c,2c+1.
// Thread (r2=tid>>3, c=tid&7): rows {rank*64+2*r2, +1}, cols [64c, 64c+64) in
// registers. 3-level shfl butterfly leaves ALL 8 lanes of a group with the 4
// final sums; each lane applies tanh and sends its 2 rows x 2 batches straight
// from registers to peer c via TWO plain st.shared::cluster.v2 (8B) stores.
// Completion: __syncthreads, then threads 0..7 do one release-arrive each on
// peer tid's count-8 mbarrier. Triple-buffered h; no tx accounting anywhere.
// Head (sign count) done in a post-kernel from g_hout.
// ---------------------------------------------------------------------------
#define SLC   68u                // padded floats per 64-col slice
#define HB    544u               // floats per batch vector (8*68)
#define BATB  2176u              // bytes per batch vector
#define BUFB  4352u              // bytes per buffer (2 batches)

__global__ void __launch_bounds__(256, 1) __cluster_dims__(8, 1, 1)
rnn_kernel(const int* __restrict__ lengths, const float* __restrict__ Whh) {
    // h index j lives at (j>>6)*SLC + (j&63)
    __shared__ __align__(16) float hbuf[3][2][HB];
    __shared__ __align__(8) unsigned long long mbars[3];

    const int tid = threadIdx.x;
    const uint32_t rank = ctarank();
    const int cl = blockIdx.x >> 3;
    const int b0 = cl * 2, b1 = b0 + 1;
    const int len0 = lengths[b0], len1 = lengths[b1];
    const int tmax = (len0 > len1) ? len0 : len1;

    const int r2 = tid >> 3;         // 0..31 : row-pair index
    const int c  = tid & 7;          // 0..7  : 64-col slice AND destination peer
    const int rowBase = (int)rank * 64 + 2 * r2;

    // ---- W_hh rows (2 x 64 cols) -> 64 packed f32x2 regs ----
    unsigned long long wA[32], wB[32];
    {
        const double2* pA = (const double2*)(Whh + (size_t)rowBase * HH + 64 * c);
        const double2* pB = (const double2*)(Whh + (size_t)(rowBase + 1) * HH + 64 * c);
#pragma unroll
        for (int i = 0; i < 16; ++i) {
            double2 a = pA[i], b = pB[i];
            wA[2 * i]     = __double_as_longlong(a.x);
            wA[2 * i + 1] = __double_as_longlong(a.y);
            wB[2 * i]     = __double_as_longlong(b.x);
            wB[2 * i + 1] = __double_as_longlong(b.y);
        }
    }

    // ---- init: zero buf 0 (both batches), init mbarriers (count = 8 arrives) ----
    {
        float* hz = &hbuf[0][0][0];
        for (int i = tid; i < (int)(2 * HB); i += 256) hz[i] = 0.f;
    }
    const uint32_t mb_local = smem_u32(&mbars[0]);
    if (tid == 0) {
        mbar_init(mb_local + 0, 8);
        mbar_init(mb_local + 8, 8);
        mbar_init(mb_local + 16, 8);
    }
    __syncthreads();
    cluster_sync_();                 // init + zero visible cluster-wide

    // remote destinations: our row-pair lands at float index rank*68 + 2*r2
    const uint32_t dst_idx = ((uint32_t)rank * SLC + 2u * (uint32_t)r2) * 4u;
    const uint32_t peer_h = mapa_u32(smem_u32(&hbuf[0][0][0]), (uint32_t)c) + dst_idx;
    uint32_t peer_mb = 0;
    if (tid < 8) peer_mb = mapa_u32(mb_local, (uint32_t)tid);

    const float* pb0 = g_pre + (size_t)b0 * TT * HH;
    const float* pb1 = g_pre + (size_t)b1 * TT * HH;

    float2 hr0 = {0.f, 0.f};          // frozen h for our 2 rows, batch 0
    float2 hr1 = {0.f, 0.f};          // batch 1
    float2 pc0 = *(const float2*)(pb0 + rowBase);
    float2 pc1 = *(const float2*)(pb1 + rowBase);

    int parbits = 0;                  // parity of mbar k in bit k
    int p3 = 0;
    for (int t = 0; t < tmax; ++t) {
        const int q3 = (p3 == 2) ? 0 : p3 + 1;

        if (t > 0) {
            mbar_wait(mb_local + (uint32_t)p3 * 8u, (uint32_t)((parbits >> p3) & 1));
            parbits ^= 1 << p3;
        }

        // prefetch next pre (hidden under FMA)
        const int tn = (t + 1 < tmax) ? (t + 1) : t;
        float2 pn0 = *(const float2*)(pb0 + (size_t)tn * HH + rowBase);
        float2 pn1 = *(const float2*)(pb1 + (size_t)tn * HH + rowBase);

        // matvec: 2 rows x 64 cols x 2 batches (conflict-free broadcast LDS)
        const ulonglong2* h0 = (const ulonglong2*)&hbuf[p3][0][SLC * c];
        const ulonglong2* h1 = (const ulonglong2*)&hbuf[p3][1][SLC * c];
        unsigned long long aA0 = 0, aB0 = 0, aA1 = 0, aB1 = 0;
#pragma unroll
        for (int k = 0; k < 16; ++k) {
            ulonglong2 x0 = h0[k];
            ulonglong2 x1 = h1[k];
            fma2(aA0, wA[2 * k], x0.x); fma2(aA0, wA[2 * k + 1], x0.y);
            fma2(aB0, wB[2 * k], x0.x); fma2(aB0, wB[2 * k + 1], x0.y);
            fma2(aA1, wA[2 * k], x1.x); fma2(aA1, wA[2 * k + 1], x1.y);
            fma2(aB1, wB[2 * k], x1.x); fma2(aB1, wB[2 * k + 1], x1.y);
        }
        float sA0 = hsum2(aA0), sB0 = hsum2(aB0);
        float sA1 = hsum2(aA1), sB1 = hsum2(aB1);
#pragma unroll
        for (int m = 1; m < 8; m <<= 1) {
            sA0 += __shfl_xor_sync(0xffffffffu, sA0, m);
            sB0 += __shfl_xor_sync(0xffffffffu, sB0, m);
            sA1 += __shfl_xor_sync(0xffffffffu, sA1, m);
            sB1 += __shfl_xor_sync(0xffffffffu, sB1, m);
        }
        // every lane now has all 4 sums; compute (identical) tanh + mask
        if (t < len0) { hr0.x = ftanh(pc0.x + sA0); hr0.y = ftanh(pc0.y + sB0); }
        if (t < len1) { hr1.x = ftanh(pc1.x + sA1); hr1.y = ftanh(pc1.y + sB1); }

        // publish straight from registers: lane c -> peer c, buffer q3
        const uint32_t dst = peer_h + (uint32_t)q3 * BUFB;
        stc2(dst,        hr0.x, hr0.y);
        stc2(dst + BATB, hr1.x, hr1.y);

        // stream h(t) to global for the post-kernel head (lanes 0/1 only)
        if (c == 0)
            *(float2*)(g_hout + (size_t)b0 * TT * HH + (size_t)t * HH + rowBase) = hr0;
        if (c == 1)
            *(float2*)(g_hout + (size_t)b1 * TT * HH + (size_t)t * HH + rowBase) = hr1;

        __syncthreads();
        if (tid < 8) mbar_arrive_remote(peer_mb + (uint32_t)q3 * 8u);

        pc0 = pn0; pc1 = pn1;
        p3 = q3;
    }

    cluster_sync_();   // drain in-flight DSMEM stores before any CTA exits
}

// ---------------------------------------------------------------------------
// Post-kernel head: counts = sum_t<len (h(t).v + c > 0), h_final = h[len-1].
// grid (4, BB): 4 t-range quarters per batch; counts via atomicAdd (exact ints).
// ---------------------------------------------------------------------------
__global__ void __launch_bounds__(256) count_kernel(const int* __restrict__ lengths,
                                                    float* __restrict__ out, int out_size) {
    const int b = blockIdx.y;
    const int quarter = blockIdx.x;
    const int len = lengths[b];
    const int t0 = quarter * (TT / 4), t1 = t0 + TT / 4;
    const int tid = threadIdx.x, lane = tid & 31, wid = tid >> 5;

    float4 v[4];
#pragma unroll
    for (int i = 0; i < 4; ++i) v[i] = *(const float4*)(g_v + lane * 16 + i * 4);
    const float c = g_c;
    const float* hb = g_hout + (size_t)b * TT * HH;

    const int tend = (t1 < len) ? t1 : len;
    int cnt = 0;
    for (int t = t0 + wid; t < tend; t += 8) {
        const float4* hp = (const float4*)(hb + (size_t)t * HH + lane * 16);
        float d = 0.f;
#pragma unroll
        for (int i = 0; i < 4; ++i) {
            float4 h4 = hp[i];
            d = fmaf(h4.x, v[i].x, d); d = fmaf(h4.y, v[i].y, d);
            d = fmaf(h4.z, v[i].z, d); d = fmaf(h4.w, v[i].w, d);
        }
#pragma unroll
        for (int m = 1; m < 32; m <<= 1) d += __shfl_xor_sync(0xffffffffu, d, m);
        if (lane == 0 && d + c > 0.f) cnt++;
    }
    __shared__ int wcnt[8];
    if (lane == 0) wcnt[wid] = cnt;
    __syncthreads();
    if (tid == 0) {
        int sum = 0;
#pragma unroll
        for (int i = 0; i < 8; ++i) sum += wcnt[i];
        if (sum) atomicAdd(&out[b], (float)sum);
    }

    if (out_size >= BB + BB * HH) {
        const int tf = len - 1;
        if (tf >= t0 && tf < t1) {
            for (int j = tid; j < HH; j += 256)
                out[BB + (size_t)b * HH + j] = hb[(size_t)tf * HH + j];
        }
    }
}

// ---------------------------------------------------------------------------
// launch
// ---------------------------------------------------------------------------
extern "C" void kernel_launch(void* const* d_in, const int* in_sizes, int n_in,
                              void* d_out, int out_size) {
    const float* x     = (const float*)d_in[0];
    const int* lengths = (const int*)d_in[1];
    const float* W_ih  = (const float*)d_in[2];
    const float* W_hh  = (const float*)d_in[3];
    const float* b_ih  = (const float*)d_in[4];
    const float* b_hh  = (const float*)d_in[5];
    const float* W1    = (const float*)d_in[6];
    const float* b1    = (const float*)d_in[7];
    const float* W2    = (const float*)d_in[8];
    const float* b2    = (const float*)d_in[9];
    float* out = (float*)d_out;

    // ncu alignment: with -s 5, launch index 5 below is rnn_kernel
    dummy_k<<<1, 32>>>();
    dummy_k<<<1, 32>>>();
    dummy_k<<<1, 32>>>();

    vc_kernel<<<1, 512>>>(W1, b1, W2, b2, out);

    dim3 ggrid(HH / 64, (BB * TT) / 64);   // (8, 1024)
    pre_gemm<<<ggrid, 256>>>(x, W_ih, b_ih, b_hh);

    rnn_kernel<<<128, 256>>>(lengths, W_hh);

    count_kernel<<<dim3(4, BB), 256>>>(lengths, out, out_size);
}

// round 12
// speedup vs baseline: 1.2533x; 1.1092x over previous
#include <cuda_runtime.h>
#include <cstdint>

#define BB 32
#define TT 2048
#define FF 128
#define HH 512

// 128 MB scratch each
__device__ float g_pre[BB * TT * HH];    // pre[b][t][h] = x W_ih^T + b_ih + b_hh
__device__ float g_hout[BB * TT * HH];   // h(t) per batch (frozen past len)
__device__ float g_v[HH];
__device__ float g_c;

// ---------------------------------------------------------------------------
// helpers
// ---------------------------------------------------------------------------
__device__ __forceinline__ uint32_t smem_u32(const void* p) {
    uint32_t a;
    asm("{ .reg .u64 t; cvta.to.shared.u64 t, %1; cvt.u32.u64 %0, t; }" : "=r"(a) : "l"(p));
    return a;
}
__device__ __forceinline__ uint32_t ctarank() {
    uint32_t r; asm("mov.u32 %0, %%cluster_ctarank;" : "=r"(r)); return r;
}
__device__ __forceinline__ uint32_t mapa_u32(uint32_t a, uint32_t r) {
    uint32_t o; asm("mapa.shared::cluster.u32 %0, %1, %2;" : "=r"(o) : "r"(a), "r"(r)); return o;
}
__device__ __forceinline__ void cluster_sync_() {
    asm volatile("barrier.cluster.arrive.aligned;" ::: "memory");
    asm volatile("barrier.cluster.wait.aligned;" ::: "memory");
}
__device__ __forceinline__ void fma2(unsigned long long& acc, unsigned long long a,
                                     unsigned long long b) {
    asm("fma.rn.f32x2 %0, %1, %2, %0;" : "+l"(acc) : "l"(a), "l"(b));
}
__device__ __forceinline__ float hsum2(unsigned long long a) {
    float lo = __uint_as_float((unsigned)(a & 0xffffffffull));
    float hi = __uint_as_float((unsigned)(a >> 32));
    return lo + hi;
}
__device__ __forceinline__ float ftanh(float x) {
    float e = __expf(2.0f * x);
    return 1.0f - __fdividef(2.0f, e + 1.0f);
}
__device__ __forceinline__ void mbar_init(uint32_t a, uint32_t cnt) {
    asm volatile("mbarrier.init.shared.b64 [%0], %1;" :: "r"(a), "r"(cnt) : "memory");
}
__device__ __forceinline__ void mbar_arrive_expect(uint32_t a, uint32_t tx) {
    asm volatile("mbarrier.arrive.expect_tx.shared.b64 _, [%0], %1;" :: "r"(a), "r"(tx) : "memory");
}
__device__ __forceinline__ void mbar_wait(uint32_t a, uint32_t parity) {
    asm volatile(
        "{\n\t.reg .pred P;\n"
        "W_%=:\n\t"
        "mbarrier.try_wait.parity.acquire.cluster.shared::cta.b64 P, [%0], %1, 0x989680;\n\t"
        "@!P bra W_%=;\n\t"
        "}" :: "r"(a), "r"(parity) : "memory");
}
// remote DSMEM 16B store with tx-counted completion on the peer's mbarrier
__device__ __forceinline__ void st_async16(uint32_t raddr, float a, float b, float c, float d,
                                           uint32_t rmbar) {
    asm volatile(
        "st.async.shared::cluster.mbarrier::complete_tx::bytes.v4.b32 [%0], {%1,%2,%3,%4}, [%5];"
        :: "r"(raddr), "r"(__float_as_uint(a)), "r"(__float_as_uint(b)),
           "r"(__float_as_uint(c)), "r"(__float_as_uint(d)), "r"(rmbar) : "memory");
}

// ---------------------------------------------------------------------------
// v = W2 @ W1 (R^512), c = b2 + W2.b1 ; also zero the count outputs
// ---------------------------------------------------------------------------
__global__ void vc_kernel(const float* __restrict__ W1, const float* __restrict__ b1,
                          const float* __restrict__ W2, const float* __restrict__ b2,
                          float* __restrict__ out) {
    __shared__ float w2s[FF];
    int tid = threadIdx.x;
    if (tid < FF) w2s[tid] = W2[tid];
    if (tid < BB) out[tid] = 0.f;
    __syncthreads();
    if (tid < HH) {
        float s = 0.f;
#pragma unroll 16
        for (int f = 0; f < FF; ++f) s = fmaf(w2s[f], W1[f * HH + tid], s);
        g_v[tid] = s;
    }
    if (tid == 0) {
        float s = b2[0];
        for (int f = 0; f < FF; ++f) s = fmaf(w2s[f], b1[f], s);
        g_c = s;
    }
}

// ---------------------------------------------------------------------------
// Input projection GEMM: [B*T,128] @ [128,512]^T + bias -> g_pre.
// ---------------------------------------------------------------------------
__global__ void __launch_bounds__(256) pre_gemm(const float* __restrict__ x,
                                                const float* __restrict__ Wih,
                                                const float* __restrict__ bih,
                                                const float* __restrict__ bhh) {
    __shared__ float xsT[32][68];
    __shared__ float wsT[32][68];
    const int tid = threadIdx.x;
    const int tx = tid & 15, ty = tid >> 4;
    const int m0 = blockIdx.y << 6;
    const int n0 = blockIdx.x << 6;
    float acc[4][4] = {};
    for (int k0 = 0; k0 < FF; k0 += 32) {
#pragma unroll
        for (int i = 0; i < 8; ++i) {
            int e = (i << 8) + tid;
            int r = e >> 5, cc = e & 31;
            xsT[cc][r] = x[(size_t)(m0 + r) * FF + k0 + cc];
            wsT[cc][r] = Wih[(size_t)(n0 + r) * FF + k0 + cc];
        }
        __syncthreads();
#pragma unroll
        for (int kk = 0; kk < 32; ++kk) {
            float4 a = *(const float4*)&xsT[kk][ty << 2];
            float4 b = *(const float4*)&wsT[kk][tx << 2];
            acc[0][0] = fmaf(a.x, b.x, acc[0][0]); acc[0][1] = fmaf(a.x, b.y, acc[0][1]);
            acc[0][2] = fmaf(a.x, b.z, acc[0][2]); acc[0][3] = fmaf(a.x, b.w, acc[0][3]);
            acc[1][0] = fmaf(a.y, b.x, acc[1][0]); acc[1][1] = fmaf(a.y, b.y, acc[1][1]);
            acc[1][2] = fmaf(a.y, b.z, acc[1][2]); acc[1][3] = fmaf(a.y, b.w, acc[1][3]);
            acc[2][0] = fmaf(a.z, b.x, acc[2][0]); acc[2][1] = fmaf(a.z, b.y, acc[2][1]);
            acc[2][2] = fmaf(a.z, b.z, acc[2][2]); acc[2][3] = fmaf(a.z, b.w, acc[2][3]);
            acc[3][0] = fmaf(a.w, b.x, acc[3][0]); acc[3][1] = fmaf(a.w, b.y, acc[3][1]);
            acc[3][2] = fmaf(a.w, b.z, acc[3][2]); acc[3][3] = fmaf(a.w, b.w, acc[3][3]);
        }
        __syncthreads();
    }
    const int n = n0 + (tx << 2);
    float4 bias;
    bias.x = bih[n + 0] + bhh[n + 0];
    bias.y = bih[n + 1] + bhh[n + 1];
    bias.z = bih[n + 2] + bhh[n + 2];
    bias.w = bih[n + 3] + bhh[n + 3];
#pragma unroll
    for (int i = 0; i < 4; ++i) {
        int m = m0 + (ty << 2) + i;
        float4 o;
        o.x = acc[i][0] + bias.x;
        o.y = acc[i][1] + bias.y;
        o.z = acc[i][2] + bias.z;
        o.w = acc[i][3] + bias.w;
        *(float4*)&g_pre[(size_t)m * HH + n] = o;
    }
}

// ---------------------------------------------------------------------------
// Persistent recurrence: 16 clusters x 8 CTAs, cluster c owns batches 2c,2c+1.
// Thread (r2=tid>>3, c=tid&7): rows {rank*64+2*r2,+1}, cols [64c,+64) in regs.
// 3-level butterfly leaves all 8 lanes of a group with all 4 sums; one xor-8
// shfl exchange packs 4 contiguous rows per lane; each thread issues exactly
// ONE st.async.v4 (16B, data+tx-signal fused, single hop). Per-batch mbarriers
// (6 total): 128 tx-updates per mbar per step (vs 512 in R4). Batch-staggered:
// wait(b0)/compute(b0)/send(b0) then wait(b1)/... so b0's messages fly while
// b1 computes. Triple-buffered h; NO CTA barrier in the loop.
// ---------------------------------------------------------------------------
#define SLC   68u                // padded floats per 64-col slice
#define HB    544u               // floats per batch vector (8*68)
#define BATB  2176u              // bytes per batch vector
#define BUFB  4352u              // bytes per buffer (2 batches)
#define EXP_TX 2048u             // 8 peers * 16 msgs * 16B per batch-mbar per step

__global__ void __launch_bounds__(256, 1) __cluster_dims__(8, 1, 1)
rnn_kernel(const int* __restrict__ lengths, const float* __restrict__ Whh) {
    // h index j lives at (j>>6)*SLC + (j&63)
    __shared__ __align__(16) float hbuf[3][2][HB];
    __shared__ __align__(8) unsigned long long mbars[6];   // [batch*3 + buf]

    const int tid = threadIdx.x;
    const uint32_t rank = ctarank();
    const int cl = blockIdx.x >> 3;
    const int b0 = cl * 2, b1 = b0 + 1;
    const int len0 = lengths[b0], len1 = lengths[b1];
    const int tmax = (len0 > len1) ? len0 : len1;

    const int r2 = tid >> 3;         // 0..31 : row-pair index
    const int c  = tid & 7;          // 0..7  : 64-col slice AND destination peer
    const int rowBase = (int)rank * 64 + 2 * r2;
    const int myb = r2 & 1;          // which batch this lane's v4 message carries

    // ---- W_hh rows (2 x 64 cols) -> 64 packed f32x2 regs ----
    unsigned long long wA[32], wB[32];
    {
        const double2* pA = (const double2*)(Whh + (size_t)rowBase * HH + 64 * c);
        const double2* pB = (const double2*)(Whh + (size_t)(rowBase + 1) * HH + 64 * c);
#pragma unroll
        for (int i = 0; i < 16; ++i) {
            double2 a = pA[i], b = pB[i];
            wA[2 * i]     = __double_as_longlong(a.x);
            wA[2 * i + 1] = __double_as_longlong(a.y);
            wB[2 * i]     = __double_as_longlong(b.x);
            wB[2 * i + 1] = __double_as_longlong(b.y);
        }
    }

    // ---- init: zero buf 0 (both batches), init 6 mbarriers ----
    {
        float* hz = &hbuf[0][0][0];
        for (int i = tid; i < (int)(2 * HB); i += 256) hz[i] = 0.f;
    }
    const uint32_t mb_local = smem_u32(&mbars[0]);
    if (tid == 0) {
#pragma unroll
        for (int k = 0; k < 6; ++k) mbar_init(mb_local + (uint32_t)k * 8u, 1);
    }
    __syncthreads();
    cluster_sync_();                 // init + zero visible cluster-wide
    if (tid == 0) {
#pragma unroll
        for (int k = 0; k < 6; ++k) mbar_arrive_expect(mb_local + (uint32_t)k * 8u, EXP_TX);
    }

    // remote destinations: this lane's 4-row pack (rows 4k..4k+3, k=r2>>1, batch myb)
    // lands at peer c, float index rank*68 + 4k, batch region myb.
    const uint32_t dst_off = (rank * SLC + 4u * (uint32_t)(r2 >> 1)) * 4u + (uint32_t)myb * BATB;
    const uint32_t peer_h  = mapa_u32(smem_u32(&hbuf[0][0][0]), (uint32_t)c) + dst_off;
    const uint32_t peer_mb = mapa_u32(mb_local, (uint32_t)c) + (uint32_t)myb * 24u;

    const float* pb0 = g_pre + (size_t)b0 * TT * HH;
    const float* pb1 = g_pre + (size_t)b1 * TT * HH;

    float2 hr0 = {0.f, 0.f};          // frozen h for our 2 rows, batch 0
    float2 hr1 = {0.f, 0.f};          // batch 1
    float2 pc0 = *(const float2*)(pb0 + rowBase);
    float2 pc1 = *(const float2*)(pb1 + rowBase);

    int parbits = 0;                  // parity of buf k in bit k (both batch mbars together)
    int p3 = 0;
    for (int t = 0; t <= tmax; ++t) {
        const int q3 = (p3 == 2) ? 0 : p3 + 1;
        const int par = (parbits >> p3) & 1;
        const uint32_t mbA = mb_local + (uint32_t)p3 * 8u;          // batch0, buf p3
        const uint32_t mbB = mb_local + (uint32_t)(3 + p3) * 8u;    // batch1, buf p3

        // ================= batch 0 =================
        if (t > 0) {
            mbar_wait(mbA, (uint32_t)par);
            if (tid == 0) mbar_arrive_expect(mbA, EXP_TX);
        }
        if (t < tmax) {
            const int tn = (t + 1 < tmax) ? (t + 1) : t;
            float2 pn0 = *(const float2*)(pb0 + (size_t)tn * HH + rowBase);

            const ulonglong2* h0 = (const ulonglong2*)&hbuf[p3][0][SLC * c];
            unsigned long long aA = 0, aB = 0;
#pragma unroll
            for (int k = 0; k < 16; ++k) {
                ulonglong2 x = h0[k];
                fma2(aA, wA[2 * k], x.x); fma2(aA, wA[2 * k + 1], x.y);
                fma2(aB, wB[2 * k], x.x); fma2(aB, wB[2 * k + 1], x.y);
            }
            float sA = hsum2(aA), sB = hsum2(aB);
#pragma unroll
            for (int m = 1; m < 8; m <<= 1) {
                sA += __shfl_xor_sync(0xffffffffu, sA, m);
                sB += __shfl_xor_sync(0xffffffffu, sB, m);
            }
            if (t < len0) { hr0.x = ftanh(pc0.x + sA); hr0.y = ftanh(pc0.y + sB); }

            // pack 4 contiguous rows: exchange pair values across xor-8 (r2 bit 0)
            float ex = __shfl_xor_sync(0xffffffffu, hr0.x, 8);
            float ey = __shfl_xor_sync(0xffffffffu, hr0.y, 8);
            if (myb == 0)   // even r2: rows 4k..4k+3 batch0 = (own pair, partner pair)
                st_async16(peer_h + (uint32_t)q3 * BUFB, hr0.x, hr0.y, ex, ey,
                           peer_mb + (uint32_t)q3 * 8u);

            if (c == 0)
                *(float2*)(g_hout + (size_t)b0 * TT * HH + (size_t)t * HH + rowBase) = hr0;
            pc0 = pn0;
        }

        // ================= batch 1 =================
        if (t > 0) {
            mbar_wait(mbB, (uint32_t)par);
            if (tid == 0) mbar_arrive_expect(mbB, EXP_TX);
            parbits ^= 1 << p3;
        }
        if (t < tmax) {
            const int tn = (t + 1 < tmax) ? (t + 1) : t;
            float2 pn1 = *(const float2*)(pb1 + (size_t)tn * HH + rowBase);

            const ulonglong2* h1 = (const ulonglong2*)&hbuf[p3][1][SLC * c];
            unsigned long long aA = 0, aB = 0;
#pragma unroll
            for (int k = 0; k < 16; ++k) {
                ulonglong2 x = h1[k];
                fma2(aA, wA[2 * k], x.x); fma2(aA, wA[2 * k + 1], x.y);
                fma2(aB, wB[2 * k], x.x); fma2(aB, wB[2 * k + 1], x.y);
            }
            float sA = hsum2(aA), sB = hsum2(aB);
#pragma unroll
            for (int m = 1; m < 8; m <<= 1) {
                sA += __shfl_xor_sync(0xffffffffu, sA, m);
                sB += __shfl_xor_sync(0xffffffffu, sB, m);
            }
            if (t < len1) { hr1.x = ftanh(pc1.x + sA); hr1.y = ftanh(pc1.y + sB); }

            float ex = __shfl_xor_sync(0xffffffffu, hr1.x, 8);
            float ey = __shfl_xor_sync(0xffffffffu, hr1.y, 8);
            if (myb == 1)   // odd r2: rows 4k..4k+3 batch1 = (partner pair, own pair)
                st_async16(peer_h + (uint32_t)q3 * BUFB, ex, ey, hr1.x, hr1.y,
                           peer_mb + (uint32_t)q3 * 8u);

            if (c == 1)
                *(float2*)(g_hout + (size_t)b1 * TT * HH + (size_t)t * HH + rowBase) = hr1;
            pc1 = pn1;
        }

        p3 = q3;
    }

    cluster_sync_();   // drain in-flight DSMEM stores before any CTA exits
}

// ---------------------------------------------------------------------------
// Post-kernel head: counts = sum_t<len (h(t).v + c > 0), h_final = h[len-1].
// grid (4, BB): 4 t-range quarters per batch; counts via atomicAdd (exact ints).
// ---------------------------------------------------------------------------
__global__ void __launch_bounds__(256) count_kernel(const int* __restrict__ lengths,
                                                    float* __restrict__ out, int out_size) {
    const int b = blockIdx.y;
    const int quarter = blockIdx.x;
    const int len = lengths[b];
    const int t0 = quarter * (TT / 4), t1 = t0 + TT / 4;
    const int tid = threadIdx.x, lane = tid & 31, wid = tid >> 5;

    float4 v[4];
#pragma unroll
    for (int i = 0; i < 4; ++i) v[i] = *(const float4*)(g_v + lane * 16 + i * 4);
    const float c = g_c;
    const float* hb = g_hout + (size_t)b * TT * HH;

    const int tend = (t1 < len) ? t1 : len;
    int cnt = 0;
    for (int t = t0 + wid; t < tend; t += 8) {
        const float4* hp = (const float4*)(hb + (size_t)t * HH + lane * 16);
        float d = 0.f;
#pragma unroll
        for (int i = 0; i < 4; ++i) {
            float4 h4 = hp[i];
            d = fmaf(h4.x, v[i].x, d); d = fmaf(h4.y, v[i].y, d);
            d = fmaf(h4.z, v[i].z, d); d = fmaf(h4.w, v[i].w, d);
        }
#pragma unroll
        for (int m = 1; m < 32; m <<= 1) d += __shfl_xor_sync(0xffffffffu, d, m);
        if (lane == 0 && d + c > 0.f) cnt++;
    }
    __shared__ int wcnt[8];
    if (lane == 0) wcnt[wid] = cnt;
    __syncthreads();
    if (tid == 0) {
        int sum = 0;
#pragma unroll
        for (int i = 0; i < 8; ++i) sum += wcnt[i];
        if (sum) atomicAdd(&out[b], (float)sum);
    }

    if (out_size >= BB + BB * HH) {
        const int tf = len - 1;
        if (tf >= t0 && tf < t1) {
            for (int j = tid; j < HH; j += 256)
                out[BB + (size_t)b * HH + j] = hb[(size_t)tf * HH + j];
        }
    }
}

// ---------------------------------------------------------------------------
// launch
// ---------------------------------------------------------------------------
extern "C" void kernel_launch(void* const* d_in, const int* in_sizes, int n_in,
                              void* d_out, int out_size) {
    const float* x     = (const float*)d_in[0];
    const int* lengths = (const int*)d_in[1];
    const float* W_ih  = (const float*)d_in[2];
    const float* W_hh  = (const float*)d_in[3];
    const float* b_ih  = (const float*)d_in[4];
    const float* b_hh  = (const float*)d_in[5];
    const float* W1    = (const float*)d_in[6];
    const float* b1    = (const float*)d_in[7];
    const float* W2    = (const float*)d_in[8];
    const float* b2    = (const float*)d_in[9];
    float* out = (float*)d_out;

    vc_kernel<<<1, 512>>>(W1, b1, W2, b2, out);

    dim3 ggrid(HH / 64, (BB * TT) / 64);   // (8, 1024)
    pre_gemm<<<ggrid, 256>>>(x, W_ih, b_ih, b_hh);

    rnn_kernel<<<128, 256>>>(lengths, W_hh);

    count_kernel<<<dim3(4, BB), 256>>>(lengths, out, out_size);
}

// round 13
// speedup vs baseline: 1.3326x; 1.0632x over previous
#include <cuda_runtime.h>
#include <cstdint>

#define BB 32
#define TT 2048
#define FF 128
#define HH 512

// 128 MB scratch each
__device__ float g_pre[BB * TT * HH];    // pre[b][t][h] = x W_ih^T + b_ih + b_hh
__device__ float g_hout[BB * TT * HH];   // h(t) per batch (frozen past len)
__device__ float g_v[HH];
__device__ float g_c;

// ---------------------------------------------------------------------------
// helpers
// ---------------------------------------------------------------------------
__device__ __forceinline__ uint32_t smem_u32(const void* p) {
    uint32_t a;
    asm("{ .reg .u64 t; cvta.to.shared.u64 t, %1; cvt.u32.u64 %0, t; }" : "=r"(a) : "l"(p));
    return a;
}
__device__ __forceinline__ uint32_t ctarank() {
    uint32_t r; asm("mov.u32 %0, %%cluster_ctarank;" : "=r"(r)); return r;
}
__device__ __forceinline__ uint32_t mapa_u32(uint32_t a, uint32_t r) {
    uint32_t o; asm("mapa.shared::cluster.u32 %0, %1, %2;" : "=r"(o) : "r"(a), "r"(r)); return o;
}
__device__ __forceinline__ void cluster_sync_() {
    asm volatile("barrier.cluster.arrive.aligned;" ::: "memory");
    asm volatile("barrier.cluster.wait.aligned;" ::: "memory");
}
__device__ __forceinline__ void fma2(unsigned long long& acc, unsigned long long a,
                                     unsigned long long b) {
    asm("fma.rn.f32x2 %0, %1, %2, %0;" : "+l"(acc) : "l"(a), "l"(b));
}
__device__ __forceinline__ float hsum2(unsigned long long a) {
    float lo = __uint_as_float((unsigned)(a & 0xffffffffull));
    float hi = __uint_as_float((unsigned)(a >> 32));
    return lo + hi;
}
__device__ __forceinline__ unsigned long long pk2(float lo, float hi) {
    return (unsigned long long)__float_as_uint(lo) |
           ((unsigned long long)__float_as_uint(hi) << 32);
}
__device__ __forceinline__ float ftanh(float x) {
    float e = __expf(2.0f * x);
    return 1.0f - __fdividef(2.0f, e + 1.0f);
}
__device__ __forceinline__ void mbar_init(uint32_t a, uint32_t cnt) {
    asm volatile("mbarrier.init.shared.b64 [%0], %1;" :: "r"(a), "r"(cnt) : "memory");
}
__device__ __forceinline__ void mbar_arrive_expect(uint32_t a, uint32_t tx) {
    asm volatile("mbarrier.arrive.expect_tx.shared.b64 _, [%0], %1;" :: "r"(a), "r"(tx) : "memory");
}
__device__ __forceinline__ void mbar_wait(uint32_t a, uint32_t parity) {
    asm volatile(
        "{\n\t.reg .pred P;\n"
        "W_%=:\n\t"
        "mbarrier.try_wait.parity.acquire.cluster.shared::cta.b64 P, [%0], %1, 0x989680;\n\t"
        "@!P bra W_%=;\n\t"
        "}" :: "r"(a), "r"(parity) : "memory");
}
// remote DSMEM store with tx-counted completion on the peer's mbarrier
__device__ __forceinline__ void st_async64(uint32_t raddr, unsigned long long v, uint32_t rmbar) {
    asm volatile("st.async.shared::cluster.mbarrier::complete_tx::bytes.b64 [%0], %1, [%2];"
                 :: "r"(raddr), "l"(v), "r"(rmbar) : "memory");
}

// ---------------------------------------------------------------------------
// v = W2 @ W1 (R^512), c = b2 + W2.b1 ; also zero the count outputs
// ---------------------------------------------------------------------------
__global__ void vc_kernel(const float* __restrict__ W1, const float* __restrict__ b1,
                          const float* __restrict__ W2, const float* __restrict__ b2,
                          float* __restrict__ out) {
    __shared__ float w2s[FF];
    int tid = threadIdx.x;
    if (tid < FF) w2s[tid] = W2[tid];
    if (tid < BB) out[tid] = 0.f;
    __syncthreads();
    if (tid < HH) {
        float s = 0.f;
#pragma unroll 16
        for (int f = 0; f < FF; ++f) s = fmaf(w2s[f], W1[f * HH + tid], s);
        g_v[tid] = s;
    }
    if (tid == 0) {
        float s = b2[0];
        for (int f = 0; f < FF; ++f) s = fmaf(w2s[f], b1[f], s);
        g_c = s;
    }
}

// ---------------------------------------------------------------------------
// Input projection GEMM: [B*T,128] @ [128,512]^T + bias -> g_pre.
// ---------------------------------------------------------------------------
__global__ void __launch_bounds__(256) pre_gemm(const float* __restrict__ x,
                                                const float* __restrict__ Wih,
                                                const float* __restrict__ bih,
                                                const float* __restrict__ bhh) {
    __shared__ float xsT[32][68];
    __shared__ float wsT[32][68];
    const int tid = threadIdx.x;
    const int tx = tid & 15, ty = tid >> 4;
    const int m0 = blockIdx.y << 6;
    const int n0 = blockIdx.x << 6;
    float acc[4][4] = {};
    for (int k0 = 0; k0 < FF; k0 += 32) {
#pragma unroll
        for (int i = 0; i < 8; ++i) {
            int e = (i << 8) + tid;
            int r = e >> 5, cc = e & 31;
            xsT[cc][r] = x[(size_t)(m0 + r) * FF + k0 + cc];
            wsT[cc][r] = Wih[(size_t)(n0 + r) * FF + k0 + cc];
        }
        __syncthreads();
#pragma unroll
        for (int kk = 0; kk < 32; ++kk) {
            float4 a = *(const float4*)&xsT[kk][ty << 2];
            float4 b = *(const float4*)&wsT[kk][tx << 2];
            acc[0][0] = fmaf(a.x, b.x, acc[0][0]); acc[0][1] = fmaf(a.x, b.y, acc[0][1]);
            acc[0][2] = fmaf(a.x, b.z, acc[0][2]); acc[0][3] = fmaf(a.x, b.w, acc[0][3]);
            acc[1][0] = fmaf(a.y, b.x, acc[1][0]); acc[1][1] = fmaf(a.y, b.y, acc[1][1]);
            acc[1][2] = fmaf(a.y, b.z, acc[1][2]); acc[1][3] = fmaf(a.y, b.w, acc[1][3]);
            acc[2][0] = fmaf(a.z, b.x, acc[2][0]); acc[2][1] = fmaf(a.z, b.y, acc[2][1]);
            acc[2][2] = fmaf(a.z, b.z, acc[2][2]); acc[2][3] = fmaf(a.z, b.w, acc[2][3]);
            acc[3][0] = fmaf(a.w, b.x, acc[3][0]); acc[3][1] = fmaf(a.w, b.y, acc[3][1]);
            acc[3][2] = fmaf(a.w, b.z, acc[3][2]); acc[3][3] = fmaf(a.w, b.w, acc[3][3]);
        }
        __syncthreads();
    }
    const int n = n0 + (tx << 2);
    float4 bias;
    bias.x = bih[n + 0] + bhh[n + 0];
    bias.y = bih[n + 1] + bhh[n + 1];
    bias.z = bih[n + 2] + bhh[n + 2];
    bias.w = bih[n + 3] + bhh[n + 3];
#pragma unroll
    for (int i = 0; i < 4; ++i) {
        int m = m0 + (ty << 2) + i;
        float4 o;
        o.x = acc[i][0] + bias.x;
        o.y = acc[i][1] + bias.y;
        o.z = acc[i][2] + bias.z;
        o.w = acc[i][3] + bias.w;
        *(float4*)&g_pre[(size_t)m * HH + n] = o;
    }
}

// ---------------------------------------------------------------------------
// Persistent recurrence: EXACT R4 protocol (best measured), head removed.
// 16 clusters x 8 CTAs; cluster c owns batches 2c,2c+1. Thread (g=tid>>3,
// s=tid&7): rows {rank*64+2g,+1}, cols [64s,+64) in registers. Per step:
// single mbar wait (per buffer, EXPECT_TX=4096 covering both batches), matvec,
// 12 shfls, 4 tanh, two st.async64 to peer s (data+signal fused, one hop).
// Triple-buffered; NO CTA barrier, NO atomics, NO in-loop head.
// h(t) streamed to g_hout by lanes s=0/1; head done in count_kernel.
// ---------------------------------------------------------------------------
#define SLC   68u                // padded floats per 64-col slice
#define HB    544u               // floats per batch vector (8*68)
#define BATB  2176u              // bytes per batch vector
#define BUFB  4352u              // bytes per buffer (2 batches)
#define EXP_TX 4096u             // 8 peers * 32 threads * 2 msgs * 8B per buffer per step

__global__ void __launch_bounds__(256, 1) __cluster_dims__(8, 1, 1)
rnn_kernel(const int* __restrict__ lengths, const float* __restrict__ Whh) {
    // h index j lives at (j>>6)*SLC + (j&63)
    __shared__ __align__(16) float hbuf[3][2][HB];
    __shared__ __align__(8) unsigned long long mbars[3];

    const int tid = threadIdx.x;
    const uint32_t rank = ctarank();
    const int cl = blockIdx.x >> 3;
    const int b0 = cl * 2, b1 = b0 + 1;
    const int len0 = lengths[b0], len1 = lengths[b1];
    const int tmax = (len0 > len1) ? len0 : len1;

    const int g = tid >> 3;          // 0..31 : row-pair index
    const int s = tid & 7;           // 0..7  : 64-col slice AND destination peer
    const int rowA = (int)rank * 64 + 2 * g;
    const uint32_t padA = rank * SLC + 2u * (uint32_t)g;  // padded float index of rowA
    const int hoff = s * (int)SLC;

    // ---- W_hh rows (2 x 64 cols) -> 64 packed f32x2 regs ----
    unsigned long long wA[32], wB[32];
    {
        const double2* pA = (const double2*)(Whh + (size_t)rowA * HH + 64 * s);
        const double2* pB = (const double2*)(Whh + (size_t)(rowA + 1) * HH + 64 * s);
#pragma unroll
        for (int i = 0; i < 16; ++i) {
            double2 a = pA[i], b = pB[i];
            wA[2 * i]     = __double_as_longlong(a.x);
            wA[2 * i + 1] = __double_as_longlong(a.y);
            wB[2 * i]     = __double_as_longlong(b.x);
            wB[2 * i + 1] = __double_as_longlong(b.y);
        }
    }

    // ---- init: zero buf 0 (both batches), init mbarriers ----
    {
        float* hz = &hbuf[0][0][0];
        for (int i = tid; i < (int)(2 * HB); i += 256) hz[i] = 0.f;
    }
    const uint32_t mb_local = smem_u32(&mbars[0]);
    if (tid == 0) {
        mbar_init(mb_local + 0, 1);
        mbar_init(mb_local + 8, 1);
        mbar_init(mb_local + 16, 1);
    }
    __syncthreads();
    cluster_sync_();                 // init + zero visible cluster-wide
    if (tid == 0) {                  // arm all three buffers
        mbar_arrive_expect(mb_local + 0, EXP_TX);
        mbar_arrive_expect(mb_local + 8, EXP_TX);
        mbar_arrive_expect(mb_local + 16, EXP_TX);
    }

    // remote bases: peer s receives our row-pair at padded index padA
    const uint32_t rb  = mapa_u32(smem_u32(&hbuf[0][0][0]), (uint32_t)s) + padA * 4u;
    const uint32_t rmb = mapa_u32(mb_local, (uint32_t)s);

    const float* pb0 = g_pre + (size_t)b0 * TT * HH;
    const float* pb1 = g_pre + (size_t)b1 * TT * HH;

    float hA0 = 0.f, hB0 = 0.f, hA1 = 0.f, hB1 = 0.f;
    int parbits = 0;                 // parity of buffer k in bit k
    int p3 = 0;

    float2 pc0 = *(const float2*)(pb0 + rowA);
    float2 pc1 = *(const float2*)(pb1 + rowA);

    for (int t = 0; t <= tmax; ++t) {
        const int q3 = (p3 == 2) ? 0 : p3 + 1;

        if (t > 0) {                 // consume writes from step t-1 (buffer p3)
            mbar_wait(mb_local + (uint32_t)p3 * 8u, (uint32_t)((parbits >> p3) & 1));
            parbits ^= 1 << p3;
            if (tid == 0) mbar_arrive_expect(mb_local + (uint32_t)p3 * 8u, EXP_TX);
        }

        if (t < tmax) {
            // prefetch next pre (hidden under FMA)
            const int tn = (t + 1 < tmax) ? (t + 1) : t;
            float2 pn0 = *(const float2*)(pb0 + (size_t)tn * HH + rowA);
            float2 pn1 = *(const float2*)(pb1 + (size_t)tn * HH + rowA);

            // register-resident matvec: 2 rows x 64 cols x 2 batches
            const ulonglong2* h0 = (const ulonglong2*)&hbuf[p3][0][hoff];
            const ulonglong2* h1 = (const ulonglong2*)&hbuf[p3][1][hoff];
            unsigned long long aA0 = 0ull, aB0 = 0ull, aA1 = 0ull, aB1 = 0ull;
#pragma unroll
            for (int i = 0; i < 16; ++i) {
                ulonglong2 x0 = h0[i];
                ulonglong2 x1 = h1[i];
                fma2(aA0, wA[2 * i], x0.x); fma2(aA0, wA[2 * i + 1], x0.y);
                fma2(aB0, wB[2 * i], x0.x); fma2(aB0, wB[2 * i + 1], x0.y);
                fma2(aA1, wA[2 * i], x1.x); fma2(aA1, wA[2 * i + 1], x1.y);
                fma2(aB1, wB[2 * i], x1.x); fma2(aB1, wB[2 * i + 1], x1.y);
            }
            float sA0 = hsum2(aA0), sB0 = hsum2(aB0);
            float sA1 = hsum2(aA1), sB1 = hsum2(aB1);
#pragma unroll
            for (int m = 1; m < 8; m <<= 1) {
                sA0 += __shfl_xor_sync(0xffffffffu, sA0, m);
                sB0 += __shfl_xor_sync(0xffffffffu, sB0, m);
                sA1 += __shfl_xor_sync(0xffffffffu, sA1, m);
                sB1 += __shfl_xor_sync(0xffffffffu, sB1, m);
            }
            float nA0 = ftanh(pc0.x + sA0), nB0 = ftanh(pc0.y + sB0);
            float nA1 = ftanh(pc1.x + sA1), nB1 = ftanh(pc1.y + sB1);
            if (t < len0) { hA0 = nA0; hB0 = nB0; }
            if (t < len1) { hA1 = nA1; hB1 = nB1; }

            // publish both batches' row-pair to peer s, buffer q3 (data+signal fused)
            const uint32_t dst = rb + (uint32_t)q3 * BUFB;
            const uint32_t dmb = rmb + (uint32_t)q3 * 8u;
            st_async64(dst,        pk2(hA0, hB0), dmb);
            st_async64(dst + BATB, pk2(hA1, hB1), dmb);

            // stream h(t) to global for the post-kernel head (lanes s=0/1 only)
            if (s == 0) {
                float2 v; v.x = hA0; v.y = hB0;
                *(float2*)(g_hout + (size_t)b0 * TT * HH + (size_t)t * HH + rowA) = v;
            }
            if (s == 1) {
                float2 v; v.x = hA1; v.y = hB1;
                *(float2*)(g_hout + (size_t)b1 * TT * HH + (size_t)t * HH + rowA) = v;
            }

            pc0 = pn0; pc1 = pn1;
        }

        p3 = q3;
    }

    cluster_sync_();   // drain in-flight st.async before any CTA exits
}

// ---------------------------------------------------------------------------
// Post-kernel head: counts = sum_t<len (h(t).v + c > 0), h_final = h[len-1].
// grid (4, BB): 4 t-range quarters per batch; counts via atomicAdd (exact ints).
// ---------------------------------------------------------------------------
__global__ void __launch_bounds__(256) count_kernel(const int* __restrict__ lengths,
                                                    float* __restrict__ out, int out_size) {
    const int b = blockIdx.y;
    const int quarter = blockIdx.x;
    const int len = lengths[b];
    const int t0 = quarter * (TT / 4), t1 = t0 + TT / 4;
    const int tid = threadIdx.x, lane = tid & 31, wid = tid >> 5;

    float4 v[4];
#pragma unroll
    for (int i = 0; i < 4; ++i) v[i] = *(const float4*)(g_v + lane * 16 + i * 4);
    const float c = g_c;
    const float* hb = g_hout + (size_t)b * TT * HH;

    const int tend = (t1 < len) ? t1 : len;
    int cnt = 0;
    for (int t = t0 + wid; t < tend; t += 8) {
        const float4* hp = (const float4*)(hb + (size_t)t * HH + lane * 16);
        float d = 0.f;
#pragma unroll
        for (int i = 0; i < 4; ++i) {
            float4 h4 = hp[i];
            d = fmaf(h4.x, v[i].x, d); d = fmaf(h4.y, v[i].y, d);
            d = fmaf(h4.z, v[i].z, d); d = fmaf(h4.w, v[i].w, d);
        }
#pragma unroll
        for (int m = 1; m < 32; m <<= 1) d += __shfl_xor_sync(0xffffffffu, d, m);
        if (lane == 0 && d + c > 0.f) cnt++;
    }
    __shared__ int wcnt[8];
    if (lane == 0) wcnt[wid] = cnt;
    __syncthreads();
    if (tid == 0) {
        int sum = 0;
#pragma unroll
        for (int i = 0; i < 8; ++i) sum += wcnt[i];
        if (sum) atomicAdd(&out[b], (float)sum);
    }

    if (out_size >= BB + BB * HH) {
        const int tf = len - 1;
        if (tf >= t0 && tf < t1) {
            for (int j = tid; j < HH; j += 256)
                out[BB + (size_t)b * HH + j] = hb[(size_t)tf * HH + j];
        }
    }
}

// ---------------------------------------------------------------------------
// launch
// ---------------------------------------------------------------------------
extern "C" void kernel_launch(void* const* d_in, const int* in_sizes, int n_in,
                              void* d_out, int out_size) {
    const float* x     = (const float*)d_in[0];
    const int* lengths = (const int*)d_in[1];
    const float* W_ih  = (const float*)d_in[2];
    const float* W_hh  = (const float*)d_in[3];
    const float* b_ih  = (const float*)d_in[4];
    const float* b_hh  = (const float*)d_in[5];
    const float* W1    = (const float*)d_in[6];
    const float* b1    = (const float*)d_in[7];
    const float* W2    = (const float*)d_in[8];
    const float* b2    = (const float*)d_in[9];
    float* out = (float*)d_out;

    vc_kernel<<<1, 512>>>(W1, b1, W2, b2, out);

    dim3 ggrid(HH / 64, (BB * TT) / 64);   // (8, 1024)
    pre_gemm<<<ggrid, 256>>>(x, W_ih, b_ih, b_hh);

    rnn_kernel<<<128, 256>>>(lengths, W_hh);

    count_kernel<<<dim3(4, BB), 256>>>(lengths, out, out_size);
}

// round 15
// speedup vs baseline: 1.4224x; 1.0674x over previous
#include <cuda_runtime.h>
#include <cstdint>

#define BB 32
#define TT 2048
#define FF 128
#define HH 512

// 128 MB scratch each
__device__ float g_pre[BB * TT * HH];    // pre[b][t][h] = x W_ih^T + b_ih + b_hh
__device__ float g_hout[BB * TT * HH];   // h(t) per batch (frozen past len)
__device__ float g_v[HH];
__device__ float g_c;

// ---------------------------------------------------------------------------
// helpers
// ---------------------------------------------------------------------------
__device__ __forceinline__ uint32_t smem_u32(const void* p) {
    uint32_t a;
    asm("{ .reg .u64 t; cvta.to.shared.u64 t, %1; cvt.u32.u64 %0, t; }" : "=r"(a) : "l"(p));
    return a;
}
__device__ __forceinline__ uint32_t ctarank() {
    uint32_t r; asm("mov.u32 %0, %%cluster_ctarank;" : "=r"(r)); return r;
}
__device__ __forceinline__ uint32_t mapa_u32(uint32_t a, uint32_t r) {
    uint32_t o; asm("mapa.shared::cluster.u32 %0, %1, %2;" : "=r"(o) : "r"(a), "r"(r)); return o;
}
__device__ __forceinline__ void cluster_sync_() {
    asm volatile("barrier.cluster.arrive.aligned;" ::: "memory");
    asm volatile("barrier.cluster.wait.aligned;" ::: "memory");
}
__device__ __forceinline__ void fma2(unsigned long long& acc, unsigned long long a,
                                     unsigned long long b) {
    asm("fma.rn.f32x2 %0, %1, %2, %0;" : "+l"(acc) : "l"(a), "l"(b));
}
__device__ __forceinline__ float hsum2(unsigned long long a) {
    float lo = __uint_as_float((unsigned)(a & 0xffffffffull));
    float hi = __uint_as_float((unsigned)(a >> 32));
    return lo + hi;
}
__device__ __forceinline__ float ftanh(float x) {
    float e = __expf(2.0f * x);
    return 1.0f - __fdividef(2.0f, e + 1.0f);
}
__device__ __forceinline__ void mbar_init(uint32_t a, uint32_t cnt) {
    asm volatile("mbarrier.init.shared.b64 [%0], %1;" :: "r"(a), "r"(cnt) : "memory");
}
__device__ __forceinline__ void mbar_arrive_expect(uint32_t a, uint32_t tx) {
    asm volatile("mbarrier.arrive.expect_tx.shared.b64 _, [%0], %1;" :: "r"(a), "r"(tx) : "memory");
}
__device__ __forceinline__ void mbar_wait(uint32_t a, uint32_t parity) {
    asm volatile(
        "{\n\t.reg .pred P;\n"
        "W_%=:\n\t"
        "mbarrier.try_wait.parity.acquire.cluster.shared::cta.b64 P, [%0], %1, 0x989680;\n\t"
        "@!P bra W_%=;\n\t"
        "}" :: "r"(a), "r"(parity) : "memory");
}
// remote DSMEM 16B store with tx-counted completion on the peer's mbarrier
__device__ __forceinline__ void st_async16(uint32_t raddr, float a, float b, float c, float d,
                                           uint32_t rmbar) {
    asm volatile(
        "st.async.shared::cluster.mbarrier::complete_tx::bytes.v4.b32 [%0], {%1,%2,%3,%4}, [%5];"
        :: "r"(raddr), "r"(__float_as_uint(a)), "r"(__float_as_uint(b)),
           "r"(__float_as_uint(c)), "r"(__float_as_uint(d)), "r"(rmbar) : "memory");
}

// ---------------------------------------------------------------------------
// v = W2 @ W1 (R^512), c = b2 + W2.b1 ; also zero the count outputs
// ---------------------------------------------------------------------------
__global__ void vc_kernel(const float* __restrict__ W1, const float* __restrict__ b1,
                          const float* __restrict__ W2, const float* __restrict__ b2,
                          float* __restrict__ out) {
    __shared__ float w2s[FF];
    int tid = threadIdx.x;
    if (tid < FF) w2s[tid] = W2[tid];
    if (tid < BB) out[tid] = 0.f;
    __syncthreads();
    if (tid < HH) {
        float s = 0.f;
#pragma unroll 16
        for (int f = 0; f < FF; ++f) s = fmaf(w2s[f], W1[f * HH + tid], s);
        g_v[tid] = s;
    }
    if (tid == 0) {
        float s = b2[0];
        for (int f = 0; f < FF; ++f) s = fmaf(w2s[f], b1[f], s);
        g_c = s;
    }
}

// ---------------------------------------------------------------------------
// Input projection GEMM: [B*T,128] @ [128,512]^T + bias -> g_pre.
// ---------------------------------------------------------------------------
__global__ void __launch_bounds__(256) pre_gemm(const float* __restrict__ x,
                                                const float* __restrict__ Wih,
                                                const float* __restrict__ bih,
                                                const float* __restrict__ bhh) {
    __shared__ float xsT[32][68];
    __shared__ float wsT[32][68];
    const int tid = threadIdx.x;
    const int tx = tid & 15, ty = tid >> 4;
    const int m0 = blockIdx.y << 6;
    const int n0 = blockIdx.x << 6;
    float acc[4][4] = {};
    for (int k0 = 0; k0 < FF; k0 += 32) {
#pragma unroll
        for (int i = 0; i < 8; ++i) {
            int e = (i << 8) + tid;
            int r = e >> 5, cc = e & 31;
            xsT[cc][r] = x[(size_t)(m0 + r) * FF + k0 + cc];
            wsT[cc][r] = Wih[(size_t)(n0 + r) * FF + k0 + cc];
        }
        __syncthreads();
#pragma unroll
        for (int kk = 0; kk < 32; ++kk) {
            float4 a = *(const float4*)&xsT[kk][ty << 2];
            float4 b = *(const float4*)&wsT[kk][tx << 2];
            acc[0][0] = fmaf(a.x, b.x, acc[0][0]); acc[0][1] = fmaf(a.x, b.y, acc[0][1]);
            acc[0][2] = fmaf(a.x, b.z, acc[0][2]); acc[0][3] = fmaf(a.x, b.w, acc[0][3]);
            acc[1][0] = fmaf(a.y, b.x, acc[1][0]); acc[1][1] = fmaf(a.y, b.y, acc[1][1]);
            acc[1][2] = fmaf(a.y, b.z, acc[1][2]); acc[1][3] = fmaf(a.y, b.w, acc[1][3]);
            acc[2][0] = fmaf(a.z, b.x, acc[2][0]); acc[2][1] = fmaf(a.z, b.y, acc[2][1]);
            acc[2][2] = fmaf(a.z, b.z, acc[2][2]); acc[2][3] = fmaf(a.z, b.w, acc[2][3]);
            acc[3][0] = fmaf(a.w, b.x, acc[3][0]); acc[3][1] = fmaf(a.w, b.y, acc[3][1]);
            acc[3][2] = fmaf(a.w, b.z, acc[3][2]); acc[3][3] = fmaf(a.w, b.w, acc[3][3]);
        }
        __syncthreads();
    }
    const int n = n0 + (tx << 2);
    float4 bias;
    bias.x = bih[n + 0] + bhh[n + 0];
    bias.y = bih[n + 1] + bhh[n + 1];
    bias.z = bih[n + 2] + bhh[n + 2];
    bias.w = bih[n + 3] + bhh[n + 3];
#pragma unroll
    for (int i = 0; i < 4; ++i) {
        int m = m0 + (ty << 2) + i;
        float4 o;
        o.x = acc[i][0] + bias.x;
        o.y = acc[i][1] + bias.y;
        o.z = acc[i][2] + bias.z;
        o.w = acc[i][3] + bias.w;
        *(float4*)&g_pre[(size_t)m * HH + n] = o;
    }
}

// ---------------------------------------------------------------------------
// Persistent recurrence: R13 loop (single wait/step) + R12 message packing.
// 16 clusters x 8 CTAs; thread (r2=tid>>3, c=tid&7): rows {rank*64+2r2,+1},
// cols [64c,+64) in regs. After the butterfly, one xor-8 exchange packs 4
// contiguous rows; each thread sends exactly ONE st.async.v4 (16B): even r2
// sends batch0's pack right after batch0's compute, odd r2 sends batch1's
// after batch1's compute (batch0 messages fly under batch1 compute). All 256
// messages/step target ONE mbar per buffer (EXP_TX=4096) -> one wait/step.
// Triple-buffered; no CTA barrier, no atomics, no in-loop head.
// ---------------------------------------------------------------------------
#define SLC   68u                // padded floats per 64-col slice
#define HB    544u               // floats per batch vector (8*68)
#define BATB  2176u              // bytes per batch vector
#define BUFB  4352u              // bytes per buffer (2 batches)
#define EXP_TX 4096u             // 256 msgs * 16B per buffer per step

__global__ void __launch_bounds__(256, 1) __cluster_dims__(8, 1, 1)
rnn_kernel(const int* __restrict__ lengths, const float* __restrict__ Whh) {
    // h index j lives at (j>>6)*SLC + (j&63)
    __shared__ __align__(16) float hbuf[3][2][HB];
    __shared__ __align__(8) unsigned long long mbars[3];

    const int tid = threadIdx.x;
    const uint32_t rank = ctarank();
    const int cl = blockIdx.x >> 3;
    const int b0 = cl * 2, b1 = b0 + 1;
    const int len0 = lengths[b0], len1 = lengths[b1];
    const int tmax = (len0 > len1) ? len0 : len1;

    const int r2 = tid >> 3;         // 0..31 : row-pair index
    const int c  = tid & 7;          // 0..7  : 64-col slice AND destination peer
    const int rowA = (int)rank * 64 + 2 * r2;
    const int myb = r2 & 1;          // which batch this thread's v4 message carries
    const int hoff = c * (int)SLC;

    // ---- W_hh rows (2 x 64 cols) -> 64 packed f32x2 regs ----
    unsigned long long wA[32], wB[32];
    {
        const double2* pA = (const double2*)(Whh + (size_t)rowA * HH + 64 * c);
        const double2* pB = (const double2*)(Whh + (size_t)(rowA + 1) * HH + 64 * c);
#pragma unroll
        for (int i = 0; i < 16; ++i) {
            double2 a = pA[i], b = pB[i];
            wA[2 * i]     = __double_as_longlong(a.x);
            wA[2 * i + 1] = __double_as_longlong(a.y);
            wB[2 * i]     = __double_as_longlong(b.x);
            wB[2 * i + 1] = __double_as_longlong(b.y);
        }
    }

    // ---- init: zero buf 0 (both batches), init mbarriers ----
    {
        float* hz = &hbuf[0][0][0];
        for (int i = tid; i < (int)(2 * HB); i += 256) hz[i] = 0.f;
    }
    const uint32_t mb_local = smem_u32(&mbars[0]);
    if (tid == 0) {
        mbar_init(mb_local + 0, 1);
        mbar_init(mb_local + 8, 1);
        mbar_init(mb_local + 16, 1);
    }
    __syncthreads();
    cluster_sync_();                 // init + zero visible cluster-wide
    if (tid == 0) {                  // arm all three buffers
        mbar_arrive_expect(mb_local + 0, EXP_TX);
        mbar_arrive_expect(mb_local + 8, EXP_TX);
        mbar_arrive_expect(mb_local + 16, EXP_TX);
    }

    // remote destinations: this thread's 4-row pack (rows 4k..4k+3, k=r2>>1,
    // batch myb) lands at peer c, float index rank*68+4k, batch region myb.
    const uint32_t dst_off = (rank * SLC + 4u * (uint32_t)(r2 >> 1)) * 4u + (uint32_t)myb * BATB;
    const uint32_t peer_h  = mapa_u32(smem_u32(&hbuf[0][0][0]), (uint32_t)c) + dst_off;
    const uint32_t peer_mb = mapa_u32(mb_local, (uint32_t)c);

    const float* pb0 = g_pre + (size_t)b0 * TT * HH;
    const float* pb1 = g_pre + (size_t)b1 * TT * HH;

    float2 hr0 = {0.f, 0.f};          // frozen h for our 2 rows, batch 0
    float2 hr1 = {0.f, 0.f};          // batch 1
    int parbits = 0;                  // parity of buffer k in bit k
    int p3 = 0;

    float2 pc0 = *(const float2*)(pb0 + rowA);
    float2 pc1 = *(const float2*)(pb1 + rowA);

    for (int t = 0; t <= tmax; ++t) {
        const int q3 = (p3 == 2) ? 0 : p3 + 1;

        if (t > 0) {                 // consume writes from step t-1 (buffer p3)
            mbar_wait(mb_local + (uint32_t)p3 * 8u, (uint32_t)((parbits >> p3) & 1));
            parbits ^= 1 << p3;
            if (tid == 0) mbar_arrive_expect(mb_local + (uint32_t)p3 * 8u, EXP_TX);
        }

        if (t < tmax) {
            const int tn = (t + 1 < tmax) ? (t + 1) : t;
            const uint32_t dst = peer_h + (uint32_t)q3 * BUFB;
            const uint32_t dmb = peer_mb + (uint32_t)q3 * 8u;

            // ======== batch 0: compute then send (messages fly under batch 1) ========
            {
                float2 pn0 = *(const float2*)(pb0 + (size_t)tn * HH + rowA);
                const ulonglong2* h0 = (const ulonglong2*)&hbuf[p3][0][hoff];
                unsigned long long aA = 0ull, aB = 0ull;
#pragma unroll
                for (int i = 0; i < 16; ++i) {
                    ulonglong2 x = h0[i];
                    fma2(aA, wA[2 * i], x.x); fma2(aA, wA[2 * i + 1], x.y);
                    fma2(aB, wB[2 * i], x.x); fma2(aB, wB[2 * i + 1], x.y);
                }
                float sA = hsum2(aA), sB = hsum2(aB);
#pragma unroll
                for (int m = 1; m < 8; m <<= 1) {
                    sA += __shfl_xor_sync(0xffffffffu, sA, m);
                    sB += __shfl_xor_sync(0xffffffffu, sB, m);
                }
                if (t < len0) { hr0.x = ftanh(pc0.x + sA); hr0.y = ftanh(pc0.y + sB); }

                // pack 4 contiguous rows (partner pair lives at r2^1 = xor-8 lane)
                float ex = __shfl_xor_sync(0xffffffffu, hr0.x, 8);
                float ey = __shfl_xor_sync(0xffffffffu, hr0.y, 8);
                if (myb == 0)
                    st_async16(dst, hr0.x, hr0.y, ex, ey, dmb);

                if (c == 0)
                    *(float2*)(g_hout + (size_t)b0 * TT * HH + (size_t)t * HH + rowA) = hr0;
                pc0 = pn0;
            }

            // ======== batch 1: compute then send ========
            {
                float2 pn1 = *(const float2*)(pb1 + (size_t)tn * HH + rowA);
                const ulonglong2* h1 = (const ulonglong2*)&hbuf[p3][1][hoff];
                unsigned long long aA = 0ull, aB = 0ull;
#pragma unroll
                for (int i = 0; i < 16; ++i) {
                    ulonglong2 x = h1[i];
                    fma2(aA, wA[2 * i], x.x); fma2(aA, wA[2 * i + 1], x.y);
                    fma2(aB, wB[2 * i], x.x); fma2(aB, wB[2 * i + 1], x.y);
                }
                float sA = hsum2(aA), sB = hsum2(aB);
#pragma unroll
                for (int m = 1; m < 8; m <<= 1) {
                    sA += __shfl_xor_sync(0xffffffffu, sA, m);
                    sB += __shfl_xor_sync(0xffffffffu, sB, m);
                }
                if (t < len1) { hr1.x = ftanh(pc1.x + sA); hr1.y = ftanh(pc1.y + sB); }

                float ex = __shfl_xor_sync(0xffffffffu, hr1.x, 8);
                float ey = __shfl_xor_sync(0xffffffffu, hr1.y, 8);
                if (myb == 1)
                    st_async16(dst, ex, ey, hr1.x, hr1.y, dmb);

                if (c == 1)
                    *(float2*)(g_hout + (size_t)b1 * TT * HH + (size_t)t * HH + rowA) = hr1;
                pc1 = pn1;
            }
        }

        p3 = q3;
    }

    cluster_sync_();   // drain in-flight st.async before any CTA exits
}

// ---------------------------------------------------------------------------
// Post-kernel head: counts = sum_t<len (h(t).v + c > 0), h_final = h[len-1].
// grid (4, BB): 4 t-range quarters per batch; counts via atomicAdd (exact ints).
// ---------------------------------------------------------------------------
__global__ void __launch_bounds__(256) count_kernel(const int* __restrict__ lengths,
                                                    float* __restrict__ out, int out_size) {
    const int b = blockIdx.y;
    const int quarter = blockIdx.x;
    const int len = lengths[b];
    const int t0 = quarter * (TT / 4), t1 = t0 + TT / 4;
    const int tid = threadIdx.x, lane = tid & 31, wid = tid >> 5;

    float4 v[4];
#pragma unroll
    for (int i = 0; i < 4; ++i) v[i] = *(const float4*)(g_v + lane * 16 + i * 4);
    const float c = g_c;
    const float* hb = g_hout + (size_t)b * TT * HH;

    const int tend = (t1 < len) ? t1 : len;
    int cnt = 0;
    for (int t = t0 + wid; t < tend; t += 8) {
        const float4* hp = (const float4*)(hb + (size_t)t * HH + lane * 16);
        float d = 0.f;
#pragma unroll
        for (int i = 0; i < 4; ++i) {
            float4 h4 = hp[i];
            d = fmaf(h4.x, v[i].x, d); d = fmaf(h4.y, v[i].y, d);
            d = fmaf(h4.z, v[i].z, d); d = fmaf(h4.w, v[i].w, d);
        }
#pragma unroll
        for (int m = 1; m < 32; m <<= 1) d += __shfl_xor_sync(0xffffffffu, d, m);
        if (lane == 0 && d + c > 0.f) cnt++;
    }
    __shared__ int wcnt[8];
    if (lane == 0) wcnt[wid] = cnt;
    __syncthreads();
    if (tid == 0) {
        int sum = 0;
#pragma unroll
        for (int i = 0; i < 8; ++i) sum += wcnt[i];
        if (sum) atomicAdd(&out[b], (float)sum);
    }

    if (out_size >= BB + BB * HH) {
        const int tf = len - 1;
        if (tf >= t0 && tf < t1) {
            for (int j = tid; j < HH; j += 256)
                out[BB + (size_t)b * HH + j] = hb[(size_t)tf * HH + j];
        }
    }
}

// ---------------------------------------------------------------------------
// launch
// ---------------------------------------------------------------------------
extern "C" void kernel_launch(void* const* d_in, const int* in_sizes, int n_in,
                              void* d_out, int out_size) {
    const float* x     = (const float*)d_in[0];
    const int* lengths = (const int*)d_in[1];
    const float* W_ih  = (const float*)d_in[2];
    const float* W_hh  = (const float*)d_in[3];
    const float* b_ih  = (const float*)d_in[4];
    const float* b_hh  = (const float*)d_in[5];
    const float* W1    = (const float*)d_in[6];
    const float* b1    = (const float*)d_in[7];
    const float* W2    = (const float*)d_in[8];
    const float* b2    = (const float*)d_in[9];
    float* out = (float*)d_out;

    vc_kernel<<<1, 512>>>(W1, b1, W2, b2, out);

    dim3 ggrid(HH / 64, (BB * TT) / 64);   // (8, 1024)
    pre_gemm<<<ggrid, 256>>>(x, W_ih, b_ih, b_hh);

    rnn_kernel<<<128, 256>>>(lengths, W_hh);

    count_kernel<<<dim3(4, BB), 256>>>(lengths, out, out_size);
}